// round 13
// baseline (speedup 1.0000x reference)
#include <cuda_runtime.h>
#include <cuda_bf16.h>
#include <cstdint>
#include <math.h>

// Problem constants (fixed by the reference generator)
#define DD   300
#define KPAD 320          // weight K padded to 5 chunks of 64 bf16
#define D4   75           // DD/4 (float4 groups)
#define NMAX 100000
#define EMAX 200000

// ---------------- scratch (device globals; no allocation allowed) ----------
__device__ float g_e   [(size_t)EMAX * DD];        // edge features  [E,D]
__device__ float g_act [(size_t)EMAX * DD];        // fp32 activations (pre outs / t1)
__device__ float g_tmp [(size_t)NMAX * DD];        // hh [N,D]
__device__ float g_h   [(size_t)NMAX * DD];        // node state h   [N,D]
__device__ float g_buf [(size_t)NMAX * DD];        // h + agg accumulator / addmat
__device__ float g_stats[2 * DD];                  // BN sum / sumsq
__device__ float g_hb[128];                        // concatenated head bias
__device__ __nv_bfloat16 g_whi[(size_t)DD * KPAD]; // weight^T hi split [n][k]
__device__ __nv_bfloat16 g_wlo[(size_t)DD * KPAD]; // weight^T lo split [n][k]

// ---------------- helpers ----------------------------------------------------
__device__ __forceinline__ uint32_t smem_u32(const void* p) {
    uint32_t a;
    asm("{ .reg .u64 t; cvta.to.shared.u64 t, %1; cvt.u32.u64 %0, t; }" : "=r"(a) : "l"(p));
    return a;
}
__device__ __forceinline__ void ldsm_x4(uint32_t* r, uint32_t addr) {
    asm volatile("ldmatrix.sync.aligned.m8n8.x4.shared.b16 {%0,%1,%2,%3}, [%4];"
                 : "=r"(r[0]), "=r"(r[1]), "=r"(r[2]), "=r"(r[3]) : "r"(addr));
}
__device__ __forceinline__ void mma_bf16(float* c, const uint32_t* a, const uint32_t* b) {
    asm volatile(
        "mma.sync.aligned.m16n8k16.row.col.f32.bf16.bf16.f32 "
        "{%0,%1,%2,%3}, {%4,%5,%6,%7}, {%8,%9}, {%0,%1,%2,%3};"
        : "+f"(c[0]), "+f"(c[1]), "+f"(c[2]), "+f"(c[3])
        : "r"(a[0]), "r"(a[1]), "r"(a[2]), "r"(a[3]), "r"(b[0]), "r"(b[1]));
}
__device__ __forceinline__ void cp16(uint32_t dst, const void* src, bool valid) {
    int sz = valid ? 16 : 0;
    asm volatile("cp.async.cg.shared.global [%0], [%1], 16, %2;"
                 :: "r"(dst), "l"(src), "r"(sz) : "memory");
}
__device__ __forceinline__ void cp_commit() {
    asm volatile("cp.async.commit_group;" ::: "memory");
}
template<int NWAIT> __device__ __forceinline__ void cp_wait() {
    asm volatile("cp.async.wait_group %0;" :: "n"(NWAIT) : "memory");
}
__device__ __forceinline__ unsigned pack_bf2(float a, float b) {
    unsigned lo = __bfloat16_as_ushort(__float2bfloat16(a));
    unsigned hi = __bfloat16_as_ushort(__float2bfloat16(b));
    return (hi << 16) | lo;
}

// ---------------- weight split kernels ---------------------------------------
// W [K=DD, N=DD] fp32 -> transposed split [n][k] bf16 [DD, KPAD]
__global__ void wsplit_k(const float* __restrict__ W,
                         __nv_bfloat16* __restrict__ hi, __nv_bfloat16* __restrict__ lo) {
    int idx = blockIdx.x * blockDim.x + threadIdx.x;
    if (idx >= DD * KPAD) return;
    int n = idx / KPAD, k = idx % KPAD;
    float x = (k < DD) ? W[(long)k * DD + n] : 0.f;
    __nv_bfloat16 h = __float2bfloat16(x);
    hi[idx] = h;
    lo[idx] = __float2bfloat16(x - __bfloat162float(h));
}

// heads: concat ahw [300,87] and chw [300,6] -> transposed split [93,KPAD]; fill g_hb
__global__ void hsplit_k(const float* __restrict__ ahw, const float* __restrict__ chw,
                         const float* __restrict__ ahb, const float* __restrict__ chb,
                         __nv_bfloat16* __restrict__ hi, __nv_bfloat16* __restrict__ lo) {
    int idx = blockIdx.x * blockDim.x + threadIdx.x;
    if (idx < 128) g_hb[idx] = (idx < 87) ? ahb[idx] : ((idx < 93) ? chb[idx - 87] : 0.f);
    if (idx >= 93 * KPAD) return;
    int n = idx / KPAD, k = idx % KPAD;
    float x = 0.f;
    if (k < DD) x = (n < 87) ? ahw[(long)k * 87 + n] : chw[(long)k * 6 + (n - 87)];
    __nv_bfloat16 h = __float2bfloat16(x);
    hi[idx] = h;
    lo[idx] = __float2bfloat16(x - __bfloat162float(h));
}

// ---------------- pre kernels (fp32 outputs, float4) -------------------------
// edge pre: relu(ea @ ew1 + eb1) -> fp32 [E, DD]
__global__ void edge_pre_k(const float* __restrict__ ea, const float* __restrict__ w1,
                           const float* __restrict__ b1, float* __restrict__ out, int E) {
    long idx = (long)blockIdx.x * blockDim.x + threadIdx.x;
    if (idx >= (long)E * D4) return;
    long e = idx / D4;
    int u = (int)(idx % D4);
    float a0 = ea[e*3+0], a1 = ea[e*3+1], a2 = ea[e*3+2];
    float v[4];
    #pragma unroll
    for (int j = 0; j < 4; j++) {
        int k = u * 4 + j;
        v[j] = fmaxf(a0 * w1[k] + a1 * w1[DD + k] + a2 * w1[2*DD + k] + b1[k], 0.f);
    }
    ((float4*)out)[idx] = make_float4(v[0], v[1], v[2], v[3]);
}

// node pre: relu(na @ nw1 + nb1) -> fp32 t; base emb[z] -> pbuf
__global__ void node_pre_k(const int* __restrict__ z, const float* __restrict__ ch,
                           const float* __restrict__ fc, const float* __restrict__ w1,
                           const float* __restrict__ b1, const float* __restrict__ emb,
                           float* __restrict__ t, float* __restrict__ base, int N) {
    long idx = (long)blockIdx.x * blockDim.x + threadIdx.x;
    if (idx >= (long)N * D4) return;
    long i = idx / D4;
    int u = (int)(idx % D4);
    float c0 = ch[i], f0 = fc[i];
    float v[4];
    #pragma unroll
    for (int j = 0; j < 4; j++) {
        int k = u * 4 + j;
        v[j] = fmaxf(c0 * w1[k] + f0 * w1[DD + k] + b1[k], 0.f);
    }
    ((float4*)t)[idx] = make_float4(v[0], v[1], v[2], v[3]);
    ((float4*)base)[idx] = ((const float4*)emb)[(long)z[i] * D4 + u];
}

// ---------------- mma.sync bf16x3 GEMM, fp32-A in-kernel split ---------------
// C[M,Nout] = act(A[M,DD] @ ((Whi+Wlo)[Nout,KPAD])^T + bias [+ addmat])
// Block tile 128x64, K chunk 64; 8 warps (4m x 2n), warp tile 32x32.
#define BM 128
#define BN 64
#define TSTRIDE 144
#define ABYTES (BM * TSTRIDE)
#define BBYTES (BN * TSTRIDE)
#define OFF_AH 0
#define OFF_AL ABYTES
#define OFF_BH (2 * ABYTES)
#define OFF_BL (2 * ABYTES + BBYTES)
#define BUFSZ  (2 * ABYTES + 2 * BBYTES)
#define SM_DBL (2 * BUFSZ)

__device__ __forceinline__ void stage_B(const __nv_bfloat16* __restrict__ hiP,
                                        const __nv_bfloat16* __restrict__ loP,
                                        int n0, int Nout, int kc,
                                        uint32_t sH, uint32_t sL, int tid) {
    #pragma unroll
    for (int i = tid; i < BN * 8; i += 256) {
        int row = i >> 3, u = i & 7;
        int gr = n0 + row;
        bool valid = (gr < Nout);
        long goff = (long)(valid ? gr : 0) * KPAD + kc + u * 8;
        uint32_t soff = (uint32_t)(row * TSTRIDE + u * 16);
        cp16(sH + soff, hiP + goff, valid);
        cp16(sL + soff, loP + goff, valid);
    }
}

__global__ void __launch_bounds__(256, 2)
mmagemm_k(const float* __restrict__ Af,
          const __nv_bfloat16* __restrict__ Whi, const __nv_bfloat16* __restrict__ Wlo,
          const float* __restrict__ bias, const float* __restrict__ addmat,
          float* __restrict__ C, float* __restrict__ C2, float* __restrict__ Cmir,
          int M, int Nout, int doRelu, int doStats) {
    extern __shared__ char sm[];
    const uint32_t sbase = smem_u32(sm);
    const int tid = threadIdx.x, wid = tid >> 5, lane = tid & 31;
    const int wm = wid & 3, wn = wid >> 2;
    const int m0 = blockIdx.y * BM, n0 = blockIdx.x * BN;

    float acc[2][4][4];
    #pragma unroll
    for (int i = 0; i < 2; i++)
        #pragma unroll
        for (int j = 0; j < 4; j++)
            #pragma unroll
            for (int q = 0; q < 4; q++) acc[i][j][q] = 0.f;

    const int a_row = lane & 15;
    const int a_kh  = lane >> 4;
    const int b_nin = (lane & 7) + ((lane >> 4) << 3);
    const int b_kh  = (lane >> 3) & 1;
    const uint32_t aLane = (uint32_t)((wm * 32 + a_row) * TSTRIDE + a_kh * 16);
    const uint32_t bLane = (uint32_t)((wn * 32 + b_nin) * TSTRIDE + b_kh * 16);

    float4 pf[8];
    // ldgA: fetch chunk kc (64 cols fp32) into registers
    auto ldgA = [&](int kc) {
        #pragma unroll
        for (int j = 0; j < 8; j++) {
            int idx = tid + j * 256;
            int row = idx >> 4, f = idx & 15;
            int gr = m0 + row;
            int k  = kc + f * 4;
            if (gr < M && k < DD)
                pf[j] = *(const float4*)(Af + (long)gr * DD + k);
            else
                pf[j] = make_float4(0.f, 0.f, 0.f, 0.f);
        }
    };
    // stsA: split registers to hi/lo bf16 and store into buffer at base
    auto stsA = [&](char* bufbase) {
        #pragma unroll
        for (int j = 0; j < 8; j++) {
            int idx = tid + j * 256;
            int row = idx >> 4, f = idx & 15;
            float x = pf[j].x, y = pf[j].y, zv = pf[j].z, w = pf[j].w;
            float hx = __bfloat162float(__float2bfloat16(x));
            float hy = __bfloat162float(__float2bfloat16(y));
            float hz = __bfloat162float(__float2bfloat16(zv));
            float hw = __bfloat162float(__float2bfloat16(w));
            uint2 uh = make_uint2(pack_bf2(hx, hy), pack_bf2(hz, hw));
            uint2 ul = make_uint2(pack_bf2(x - hx, y - hy), pack_bf2(zv - hz, w - hw));
            int off = row * TSTRIDE + f * 8;
            *(uint2*)(bufbase + OFF_AH + off) = uh;
            *(uint2*)(bufbase + OFF_AL + off) = ul;
        }
    };

    // prologue: chunk 0 (one-time LDG stall here is amortized)
    ldgA(0);
    stage_B(Whi, Wlo, n0, Nout, 0, sbase + OFF_BH, sbase + OFF_BL, tid);
    cp_commit();
    stsA(sm);

    #pragma unroll
    for (int c = 0; c < 5; c++) {
        char* nbuf = sm + ((c + 1) & 1) * BUFSZ;
        if (c < 4) {
            int kc = (c + 1) * 64;
            ldgA(kc);   // LDGs first — latency absorbed by the MMA loop below
            stage_B(Whi, Wlo, n0, Nout, kc,
                    smem_u32(nbuf) + OFF_BH, smem_u32(nbuf) + OFF_BL, tid);
            cp_commit();
            cp_wait<1>();
        } else {
            cp_wait<0>();
        }
        __syncthreads();   // B(c) ready; A(c) STS (prev iter) visible

        const uint32_t base = sbase + (uint32_t)((c & 1) * BUFSZ);
        const uint32_t aB = base + aLane, bB = base + bLane;
        #pragma unroll
        for (int ks = 0; ks < 4; ks++) {
            uint32_t ah[2][4], al[2][4];
            #pragma unroll
            for (int i = 0; i < 2; i++) {
                ldsm_x4(ah[i], aB + OFF_AH + i * (16 * TSTRIDE) + ks * 32);
                ldsm_x4(al[i], aB + OFF_AL + i * (16 * TSTRIDE) + ks * 32);
            }
            uint32_t bh[4][2], bl[4][2];
            #pragma unroll
            for (int jj = 0; jj < 2; jj++) {
                uint32_t t[4];
                ldsm_x4(t, bB + OFF_BH + jj * (16 * TSTRIDE) + ks * 32);
                bh[2*jj][0] = t[0]; bh[2*jj][1] = t[1];
                bh[2*jj+1][0] = t[2]; bh[2*jj+1][1] = t[3];
                ldsm_x4(t, bB + OFF_BL + jj * (16 * TSTRIDE) + ks * 32);
                bl[2*jj][0] = t[0]; bl[2*jj][1] = t[1];
                bl[2*jj+1][0] = t[2]; bl[2*jj+1][1] = t[3];
            }
            #pragma unroll
            for (int i = 0; i < 2; i++)
                #pragma unroll
                for (int j = 0; j < 4; j++) {
                    mma_bf16(acc[i][j], ah[i], bh[j]);
                    mma_bf16(acc[i][j], ah[i], bl[j]);
                    mma_bf16(acc[i][j], al[i], bh[j]);
                }
        }
        // A(c+1) split+store AFTER the MMAs — pf loads have completed by now
        if (c < 4) stsA(nbuf);
        __syncthreads();   // stsA visible; buffer reads of this iter complete
    }

    // epilogue (+ optional per-column BN statistics)
    const int g  = lane >> 2, tig = lane & 3;
    float cs[8], cq[8];
    #pragma unroll
    for (int t = 0; t < 8; t++) { cs[t] = 0.f; cq[t] = 0.f; }

    #pragma unroll
    for (int i = 0; i < 2; i++) {
        #pragma unroll
        for (int j = 0; j < 4; j++) {
            int row = m0 + wm * 32 + i * 16 + g;
            int col = n0 + wn * 32 + j * 8 + tig * 2;
            #pragma unroll
            for (int half = 0; half < 2; half++) {
                int r = row + half * 8;
                if (r >= M) continue;
                #pragma unroll
                for (int q = 0; q < 2; q++) {
                    int cc = col + q;
                    if (cc >= Nout) continue;
                    float v = acc[i][j][half * 2 + q] + bias[cc];
                    if (addmat) v += addmat[(long)r * Nout + cc];
                    if (doRelu) v = fmaxf(v, 0.f);
                    if (doStats) { cs[j*2+q] += v; cq[j*2+q] += v * v; }
                    if (C2) {
                        if (cc < 87) C[(long)r * 87 + cc] = v;
                        else         C2[(long)r * 6 + (cc - 87)] = v;
                    } else {
                        C[(long)r * Nout + cc] = v;
                        if (Cmir) Cmir[(long)r * Nout + cc] = v;
                    }
                }
            }
        }
    }

    if (doStats) {
        #pragma unroll
        for (int t = 0; t < 8; t++) {
            #pragma unroll
            for (int off = 16; off >= 4; off >>= 1) {
                cs[t] += __shfl_down_sync(0xFFFFFFFFu, cs[t], off);
                cq[t] += __shfl_down_sync(0xFFFFFFFFu, cq[t], off);
            }
        }
        float* ssm = (float*)sm;   // reuse staging smem: [64 cols][2]
        __syncthreads();
        if (tid < 128) ssm[tid] = 0.f;
        __syncthreads();
        if (g == 0) {
            #pragma unroll
            for (int j = 0; j < 4; j++)
                #pragma unroll
                for (int q = 0; q < 2; q++) {
                    int cl = wn * 32 + j * 8 + tig * 2 + q;
                    atomicAdd(&ssm[cl * 2 + 0], cs[j*2+q]);
                    atomicAdd(&ssm[cl * 2 + 1], cq[j*2+q]);
                }
        }
        __syncthreads();
        if (tid < 64) {
            int cc = n0 + tid;
            if (cc < DD) {
                atomicAdd(&g_stats[cc],      ssm[tid * 2 + 0]);
                atomicAdd(&g_stats[DD + cc], ssm[tid * 2 + 1]);
            }
        }
    }
}

// ---------------- misc elementwise kernels ----------------------------------
__global__ void zero_stats_k() {
    int t = threadIdx.x;
    if (t < 2 * DD) g_stats[t] = 0.f;
}

// buf[dst] += relu(h[src] + e)  (one warp per edge, float4)
__global__ void scatter_k(const float* __restrict__ h, const float* __restrict__ e,
                          const int* __restrict__ src, const int* __restrict__ dst,
                          float* __restrict__ buf, int E) {
    int warp = (int)(((long)blockIdx.x * blockDim.x + threadIdx.x) >> 5);
    int lane = threadIdx.x & 31;
    if (warp >= E) return;
    int s = src[warp], t = dst[warp];
    const float4* hr = (const float4*)(h) + (long)s * D4;
    const float4* er = (const float4*)(e) + (long)warp * D4;
    float* br = buf + (long)t * DD;
    for (int i = lane; i < D4; i += 32) {
        float4 hv = hr[i], ev = er[i];
        float v0 = hv.x + ev.x, v1 = hv.y + ev.y, v2 = hv.z + ev.z, v3 = hv.w + ev.w;
        if (v0 > 0.f) atomicAdd(&br[i*4+0], v0);
        if (v1 > 0.f) atomicAdd(&br[i*4+1], v1);
        if (v2 > 0.f) atomicAdd(&br[i*4+2], v2);
        if (v3 > 0.f) atomicAdd(&br[i*4+3], v3);
    }
}

// h = relu(bn(hh)); mirror into buf
__global__ void bn_apply_k(const float* __restrict__ hh, const float* __restrict__ gamma,
                           const float* __restrict__ beta, float* __restrict__ h,
                           float* __restrict__ buf, int N) {
    long idx = (long)blockIdx.x * blockDim.x + threadIdx.x;
    if (idx >= (long)N * D4) return;
    int du = (int)(idx % D4);
    float invN = 1.f / (float)N;
    float4 x = ((const float4*)hh)[idx];
    float o[4] = {x.x, x.y, x.z, x.w};
    #pragma unroll
    for (int c = 0; c < 4; c++) {
        int d = du * 4 + c;
        float mu  = g_stats[d] * invN;
        float var = g_stats[DD + d] * invN - mu * mu;
        float rstd = rsqrtf(var + 1e-5f);
        float v = (o[c] - mu) * rstd * gamma[d] + beta[d];
        o[c] = fmaxf(v, 0.f);
    }
    float4 res = make_float4(o[0], o[1], o[2], o[3]);
    ((float4*)h)[idx]   = res;
    ((float4*)buf)[idx] = res;
}

// ---------------- driver ----------------------------------------------------
static void launch_mma(const float* Af,
                       const __nv_bfloat16* whi, const __nv_bfloat16* wlo,
                       const float* bias, const float* addmat,
                       float* C, float* C2, float* Cmir,
                       int M, int Nout, int relu, int stats) {
    dim3 grid((Nout + BN - 1) / BN, (M + BM - 1) / BM);
    mmagemm_k<<<grid, 256, SM_DBL>>>(Af, whi, wlo, bias, addmat,
                                     C, C2, Cmir, M, Nout, relu, stats);
}

extern "C" void kernel_launch(void* const* d_in, const int* in_sizes, int n_in,
                              void* d_out, int out_size) {
    const int*   z    = (const int*)  d_in[0];
    const float* chir = (const float*)d_in[1];
    const float* fchg = (const float*)d_in[2];
    const int*   ei   = (const int*)  d_in[3];
    const float* ea   = (const float*)d_in[4];
    const float* emb  = (const float*)d_in[5];
    const float* nw1  = (const float*)d_in[6];
    const float* nb1  = (const float*)d_in[7];
    const float* nw2  = (const float*)d_in[8];
    const float* nb2  = (const float*)d_in[9];
    const float* ew1  = (const float*)d_in[10];
    const float* eb1  = (const float*)d_in[11];
    const float* ew2  = (const float*)d_in[12];
    const float* eb2  = (const float*)d_in[13];
    const float* gw1  = (const float*)d_in[14];
    const float* gb1  = (const float*)d_in[15];
    const float* gw2  = (const float*)d_in[16];
    const float* gb2  = (const float*)d_in[17];
    const float* gam  = (const float*)d_in[18];
    const float* bet  = (const float*)d_in[19];
    const float* ahw  = (const float*)d_in[20];
    const float* ahb  = (const float*)d_in[21];
    const float* chw  = (const float*)d_in[22];
    const float* chb  = (const float*)d_in[23];

    const int N = in_sizes[0];
    const int E = in_sizes[3] / 2;
    const int* src = ei;
    const int* dst = ei + E;

    static int smem_set = 0;
    if (!smem_set) {
        cudaFuncSetAttribute(mmagemm_k, cudaFuncAttributeMaxDynamicSharedMemorySize, SM_DBL);
        smem_set = 1;
    }

    float *pe, *pact, *phh, *ph, *pbuf, *phb;
    __nv_bfloat16 *pwhi, *pwlo;
    cudaGetSymbolAddress((void**)&pe,   g_e);
    cudaGetSymbolAddress((void**)&pact, g_act);
    cudaGetSymbolAddress((void**)&phh,  g_tmp);
    cudaGetSymbolAddress((void**)&ph,   g_h);
    cudaGetSymbolAddress((void**)&pbuf, g_buf);
    cudaGetSymbolAddress((void**)&phb,  g_hb);
    cudaGetSymbolAddress((void**)&pwhi, g_whi);
    cudaGetSymbolAddress((void**)&pwlo, g_wlo);

    const int WS_BLK = (DD * KPAD + 255) / 256;

    // ---- edge encoder: e = relu(ea @ ew1 + eb1) @ ew2 + eb2 ----
    edge_pre_k<<<(unsigned)(((long)E * D4 + 255) / 256), 256>>>(ea, ew1, eb1, pact, E);
    wsplit_k<<<WS_BLK, 256>>>(ew2, pwhi, pwlo);
    launch_mma(pact, pwhi, pwlo, eb2, nullptr, pe, nullptr, nullptr, E, DD, 0, 0);

    // ---- node init: h = emb[z] + relu(na @ nw1 + nb1) @ nw2 + nb2; mirror -> buf ----
    node_pre_k<<<(unsigned)(((long)N * D4 + 255) / 256), 256>>>(
        z, chir, fchg, nw1, nb1, emb, pact, pbuf, N);
    wsplit_k<<<WS_BLK, 256>>>(nw2, pwhi, pwlo);
    launch_mma(pact, pwhi, pwlo, nb2, pbuf, ph, nullptr, pbuf, N, DD, 0, 0);

    // ---- 5 GINE layers ----
    for (int l = 0; l < 5; l++) {
        scatter_k<<<(E + 7) / 8, 256>>>(ph, pe, src, dst, pbuf, E);
        // GEMM1: t1 = relu(buf @ W1 + b1) -> fp32 g_act
        wsplit_k<<<WS_BLK, 256>>>(gw1 + (long)l * DD * DD, pwhi, pwlo);
        launch_mma(pbuf, pwhi, pwlo, gb1 + l * DD, nullptr,
                   pact, nullptr, nullptr, N, DD, 1, 0);
        // GEMM2: hh = t1 @ W2 + b2 (fp32 out, fused BN stats)
        wsplit_k<<<WS_BLK, 256>>>(gw2 + (long)l * DD * DD, pwhi, pwlo);
        zero_stats_k<<<1, 2 * DD>>>();
        launch_mma(pact, pwhi, pwlo, gb2 + l * DD, nullptr,
                   phh, nullptr, nullptr, N, DD, 0, 1);
        // batchnorm + relu; mirror into buf
        bn_apply_k<<<(unsigned)(((long)N * D4 + 255) / 256), 256>>>(
            phh, gam + l * DD, bet + l * DD, ph, pbuf, N);
    }

    // ---- heads: one 93-col GEMM (A = h fp32), routes to the two output regions ----
    float* out = (float*)d_out;
    hsplit_k<<<(93 * KPAD + 255) / 256, 256>>>(ahw, chw, ahb, chb, pwhi, pwlo);
    launch_mma(ph, pwhi, pwlo, phb, nullptr,
               out, out + (long)N * 87, nullptr, N, 93, 0, 0);
}

// round 14
// speedup vs baseline: 1.1540x; 1.1540x over previous
#include <cuda_runtime.h>
#include <cuda_bf16.h>
#include <cstdint>
#include <math.h>

// Problem constants (fixed by the reference generator)
#define DD   300
#define KPAD 320          // K padded to 5 chunks of 64 bf16
#define KP8  40           // KPAD/8  (uint4 groups of 8 bf16)
#define D4   75           // DD/4    (float4 groups)
#define NMAX 100000
#define EMAX 200000
#define CAP  16           // bucket slots per node (deg ~ Poisson(2); overflow handled)

// ---------------- scratch (device globals; no allocation allowed) ----------
__device__ float g_e   [(size_t)EMAX * DD];        // edge features  [E,D]
__device__ float g_tmp [(size_t)NMAX * DD];        // hh [N,D]
__device__ float g_h   [(size_t)NMAX * DD];        // node state h   [N,D]
__device__ float g_buf [(size_t)NMAX * DD];        // h + agg (GEMM1 input)
__device__ float g_stats[2 * DD];                  // BN sum / sumsq
__device__ float g_hb[128];                        // concatenated head bias
__device__ __nv_bfloat16 g_ahi[(size_t)EMAX * KPAD];  // activation hi split (input A)
__device__ __nv_bfloat16 g_alo[(size_t)EMAX * KPAD];  // activation lo split
__device__ __nv_bfloat16 g_bhi[(size_t)NMAX * KPAD];  // split GEMM outputs (t1 / final h)
__device__ __nv_bfloat16 g_blo[(size_t)NMAX * KPAD];
__device__ __nv_bfloat16 g_whi[(size_t)DD * KPAD];    // weight^T hi split [n][k]
__device__ __nv_bfloat16 g_wlo[(size_t)DD * KPAD];    // weight^T lo split [n][k]
__device__ int g_deg[NMAX];                        // per-node incoming degree
__device__ int g_bucket[(size_t)NMAX * CAP];       // per-node edge ids
__device__ int g_ovf_cnt;                          // overflow edges (deg > CAP)
__device__ int g_ovf[4096];

// ---------------- helpers ----------------------------------------------------
__device__ __forceinline__ uint32_t smem_u32(const void* p) {
    uint32_t a;
    asm("{ .reg .u64 t; cvta.to.shared.u64 t, %1; cvt.u32.u64 %0, t; }" : "=r"(a) : "l"(p));
    return a;
}
__device__ __forceinline__ void ldsm_x4(uint32_t* r, uint32_t addr) {
    asm volatile("ldmatrix.sync.aligned.m8n8.x4.shared.b16 {%0,%1,%2,%3}, [%4];"
                 : "=r"(r[0]), "=r"(r[1]), "=r"(r[2]), "=r"(r[3]) : "r"(addr));
}
__device__ __forceinline__ void mma_bf16(float* c, const uint32_t* a, const uint32_t* b) {
    asm volatile(
        "mma.sync.aligned.m16n8k16.row.col.f32.bf16.bf16.f32 "
        "{%0,%1,%2,%3}, {%4,%5,%6,%7}, {%8,%9}, {%0,%1,%2,%3};"
        : "+f"(c[0]), "+f"(c[1]), "+f"(c[2]), "+f"(c[3])
        : "r"(a[0]), "r"(a[1]), "r"(a[2]), "r"(a[3]), "r"(b[0]), "r"(b[1]));
}
__device__ __forceinline__ void cp16(uint32_t dst, const void* src, bool valid) {
    int sz = valid ? 16 : 0;
    asm volatile("cp.async.cg.shared.global [%0], [%1], 16, %2;"
                 :: "r"(dst), "l"(src), "r"(sz) : "memory");
}
__device__ __forceinline__ void cp_commit() {
    asm volatile("cp.async.commit_group;" ::: "memory");
}
template<int NWAIT> __device__ __forceinline__ void cp_wait() {
    asm volatile("cp.async.wait_group %0;" :: "n"(NWAIT) : "memory");
}
__device__ __forceinline__ unsigned pack_bf2(float a, float b) {
    unsigned lo = __bfloat16_as_ushort(__float2bfloat16(a));
    unsigned hi = __bfloat16_as_ushort(__float2bfloat16(b));
    return (hi << 16) | lo;
}
// split 8 fp32 values into hi/lo uint4 (8 bf16 each)
__device__ __forceinline__ void split8(const float* v, uint4& uh, uint4& ul) {
    float h[8], l[8];
    #pragma unroll
    for (int j = 0; j < 8; j++) {
        __nv_bfloat16 hb = __float2bfloat16(v[j]);
        h[j] = __bfloat162float(hb);
        l[j] = v[j] - h[j];
    }
    uh = make_uint4(pack_bf2(h[0], h[1]), pack_bf2(h[2], h[3]),
                    pack_bf2(h[4], h[5]), pack_bf2(h[6], h[7]));
    ul = make_uint4(pack_bf2(l[0], l[1]), pack_bf2(l[2], l[3]),
                    pack_bf2(l[4], l[5]), pack_bf2(l[6], l[7]));
}

// ---------------- split kernels (vectorized: 8 bf16 per thread) -------------
// fp32 [M,DD] -> bf16 hi/lo [M,KPAD]
__global__ void split_k(const float* __restrict__ in,
                        __nv_bfloat16* __restrict__ hi, __nv_bfloat16* __restrict__ lo, int M) {
    long idx = (long)blockIdx.x * blockDim.x + threadIdx.x;
    if (idx >= (long)M * KP8) return;
    long m = idx / KP8;
    int u = (int)(idx % KP8);
    const float4* in4 = (const float4*)(in) + m * D4;
    float v[8] = {0,0,0,0,0,0,0,0};
    int f0 = u * 2;
    if (f0 < D4)     { float4 a = in4[f0];     v[0]=a.x; v[1]=a.y; v[2]=a.z; v[3]=a.w; }
    if (f0 + 1 < D4) { float4 a = in4[f0 + 1]; v[4]=a.x; v[5]=a.y; v[6]=a.z; v[7]=a.w; }
    uint4 uh, ul;
    split8(v, uh, ul);
    ((uint4*)hi)[idx] = uh;
    ((uint4*)lo)[idx] = ul;
}

// W [K=DD, N=DD] fp32 -> transposed split [n][k] bf16 [DD, KPAD]
__global__ void wsplit_k(const float* __restrict__ W,
                         __nv_bfloat16* __restrict__ hi, __nv_bfloat16* __restrict__ lo) {
    int idx = blockIdx.x * blockDim.x + threadIdx.x;
    if (idx >= DD * KPAD) return;
    int n = idx / KPAD, k = idx % KPAD;
    float x = (k < DD) ? W[(long)k * DD + n] : 0.f;
    __nv_bfloat16 h = __float2bfloat16(x);
    hi[idx] = h;
    lo[idx] = __float2bfloat16(x - __bfloat162float(h));
}

// heads: concat ahw [300,87] and chw [300,6] -> transposed split [93,KPAD]; fill g_hb
__global__ void hsplit_k(const float* __restrict__ ahw, const float* __restrict__ chw,
                         const float* __restrict__ ahb, const float* __restrict__ chb,
                         __nv_bfloat16* __restrict__ hi, __nv_bfloat16* __restrict__ lo) {
    int idx = blockIdx.x * blockDim.x + threadIdx.x;
    if (idx < 128) g_hb[idx] = (idx < 87) ? ahb[idx] : ((idx < 93) ? chb[idx - 87] : 0.f);
    if (idx >= 93 * KPAD) return;
    int n = idx / KPAD, k = idx % KPAD;
    float x = 0.f;
    if (k < DD) x = (n < 87) ? ahw[(long)k * 87 + n] : chw[(long)k * 6 + (n - 87)];
    __nv_bfloat16 h = __float2bfloat16(x);
    hi[idx] = h;
    lo[idx] = __float2bfloat16(x - __bfloat162float(h));
}

// edge pre: relu(ea @ ew1 + eb1) -> split bf16 [E,KPAD]  (8 outputs/thread)
__global__ void edge_pre_split_k(const float* __restrict__ ea, const float* __restrict__ w1,
                                 const float* __restrict__ b1,
                                 __nv_bfloat16* __restrict__ hi, __nv_bfloat16* __restrict__ lo, int E) {
    long idx = (long)blockIdx.x * blockDim.x + threadIdx.x;
    if (idx >= (long)E * KP8) return;
    long e = idx / KP8;
    int u = (int)(idx % KP8);
    float a0 = ea[e*3+0], a1 = ea[e*3+1], a2 = ea[e*3+2];
    float v[8];
    #pragma unroll
    for (int j = 0; j < 8; j++) {
        int k = u * 8 + j;
        float t = 0.f;
        if (k < DD)
            t = fmaxf(a0 * w1[k] + a1 * w1[DD + k] + a2 * w1[2*DD + k] + b1[k], 0.f);
        v[j] = t;
    }
    uint4 uh, ul;
    split8(v, uh, ul);
    ((uint4*)hi)[idx] = uh;
    ((uint4*)lo)[idx] = ul;
}

// node pre: relu(na @ nw1 + nb1) -> split; base emb[z] -> pbuf (float4 copies)
__global__ void node_pre_split_k(const int* __restrict__ z, const float* __restrict__ ch,
                                 const float* __restrict__ fc, const float* __restrict__ w1,
                                 const float* __restrict__ b1, const float* __restrict__ emb,
                                 __nv_bfloat16* __restrict__ hi, __nv_bfloat16* __restrict__ lo,
                                 float* __restrict__ base, int N) {
    long idx = (long)blockIdx.x * blockDim.x + threadIdx.x;
    if (idx >= (long)N * KP8) return;
    long i = idx / KP8;
    int u = (int)(idx % KP8);
    float c0 = ch[i], f0 = fc[i];
    float v[8];
    #pragma unroll
    for (int j = 0; j < 8; j++) {
        int k = u * 8 + j;
        v[j] = (k < DD) ? fmaxf(c0 * w1[k] + f0 * w1[DD + k] + b1[k], 0.f) : 0.f;
    }
    uint4 uh, ul;
    split8(v, uh, ul);
    ((uint4*)hi)[idx] = uh;
    ((uint4*)lo)[idx] = ul;
    const float4* er = (const float4*)(emb) + (long)z[i] * D4;
    float4* br = (float4*)(base) + i * D4;
    int g0 = u * 2;
    if (g0 < D4)     br[g0]     = er[g0];
    if (g0 + 1 < D4) br[g0 + 1] = er[g0 + 1];
}

// ---------------- bucket build (once per launch) ------------------------------
__global__ void zero_deg_k(int N) {
    int idx = blockIdx.x * blockDim.x + threadIdx.x;
    if (idx < N) g_deg[idx] = 0;
    if (idx == 0) g_ovf_cnt = 0;
}
__global__ void fill_bucket_k(const int* __restrict__ dst, int E) {
    int e = blockIdx.x * blockDim.x + threadIdx.x;
    if (e >= E) return;
    int d = dst[e];
    int slot = atomicAdd(&g_deg[d], 1);
    if (slot < CAP) {
        g_bucket[(long)d * CAP + slot] = e;
    } else {
        int o = atomicAdd(&g_ovf_cnt, 1);
        if (o < 4096) g_ovf[o] = e;
    }
}

// ---------------- gather: buf[i] = h[i] + sum_{e: dst=i} relu(h[src]+e) -------
__global__ void gather_k(const float* __restrict__ h, const float* __restrict__ e,
                         const int* __restrict__ src, float* __restrict__ buf, int N) {
    int warp = (int)(((long)blockIdx.x * blockDim.x + threadIdx.x) >> 5);
    int lane = threadIdx.x & 31;
    if (warp >= N) return;
    int d = g_deg[warp];
    if (d > CAP) d = CAP;
    const float4* hr = (const float4*)(h) + (long)warp * D4;
    float4 acc[3];
    #pragma unroll
    for (int j = 0; j < 3; j++) {
        int i4 = lane + j * 32;
        acc[j] = (i4 < D4) ? hr[i4] : make_float4(0.f, 0.f, 0.f, 0.f);
    }
    for (int t = 0; t < d; t++) {
        int eid = g_bucket[(long)warp * CAP + t];
        int s = src[eid];
        const float4* hs = (const float4*)(h) + (long)s * D4;
        const float4* er = (const float4*)(e) + (long)eid * D4;
        #pragma unroll
        for (int j = 0; j < 3; j++) {
            int i4 = lane + j * 32;
            if (i4 < D4) {
                float4 a = hs[i4], b = er[i4];
                acc[j].x += fmaxf(a.x + b.x, 0.f);
                acc[j].y += fmaxf(a.y + b.y, 0.f);
                acc[j].z += fmaxf(a.z + b.z, 0.f);
                acc[j].w += fmaxf(a.w + b.w, 0.f);
            }
        }
    }
    float4* br = (float4*)(buf) + (long)warp * D4;
    #pragma unroll
    for (int j = 0; j < 3; j++) {
        int i4 = lane + j * 32;
        if (i4 < D4) br[i4] = acc[j];
    }
}

// overflow fallback: atomic adds for the (normally zero) edges beyond CAP
__global__ void ovf_k(const float* __restrict__ h, const float* __restrict__ e,
                      const int* __restrict__ src, const int* __restrict__ dst,
                      float* __restrict__ buf) {
    int cnt = g_ovf_cnt;
    if (cnt > 4096) cnt = 4096;
    int warp = (int)((blockIdx.x * blockDim.x + threadIdx.x) >> 5);
    int lane = threadIdx.x & 31;
    int nwarp = (gridDim.x * blockDim.x) >> 5;
    for (int t = warp; t < cnt; t += nwarp) {
        int eid = g_ovf[t];
        int s = src[eid], dd = dst[eid];
        const float* hs = h + (long)s * DD;
        const float* er = e + (long)eid * DD;
        float* br = buf + (long)dd * DD;
        for (int k = lane; k < DD; k += 32) {
            float v = fmaxf(hs[k] + er[k], 0.f);
            if (v > 0.f) atomicAdd(&br[k], v);
        }
    }
}

// ---------------- mma.sync bf16x3 GEMM, cp.async double-buffered -------------
#define BM 128
#define BN 64
#define TSTRIDE 144
#define ABYTES (BM * TSTRIDE)
#define BBYTES (BN * TSTRIDE)
#define OFF_AH 0
#define OFF_AL ABYTES
#define OFF_BH (2 * ABYTES)
#define OFF_BL (2 * ABYTES + BBYTES)
#define BUFSZ  (2 * ABYTES + 2 * BBYTES)
#define SM_DBL (2 * BUFSZ)

__device__ __forceinline__ void stage_pair(const __nv_bfloat16* __restrict__ hiP,
                                           const __nv_bfloat16* __restrict__ loP,
                                           int row0, int rowMax, int kc,
                                           uint32_t sH, uint32_t sL, int rows, int tid) {
    int total = rows * 8;
    for (int i = tid; i < total; i += 256) {
        int row = i >> 3, u = i & 7;
        int gr = row0 + row;
        bool valid = (gr < rowMax);
        long goff = (long)(valid ? gr : 0) * KPAD + kc + u * 8;
        uint32_t soff = (uint32_t)(row * TSTRIDE + u * 16);
        cp16(sH + soff, hiP + goff, valid);
        cp16(sL + soff, loP + goff, valid);
    }
}

__global__ void __launch_bounds__(256, 2)
mmagemm_k(const __nv_bfloat16* __restrict__ Ahi, const __nv_bfloat16* __restrict__ Alo,
          const __nv_bfloat16* __restrict__ Whi, const __nv_bfloat16* __restrict__ Wlo,
          const float* __restrict__ bias, const float* __restrict__ addmat,
          float* __restrict__ C, float* __restrict__ C2,
          __nv_bfloat16* __restrict__ Ohi, __nv_bfloat16* __restrict__ Olo,
          int M, int Nout, int doRelu, int doStats) {
    extern __shared__ char sm[];
    const uint32_t sbase = smem_u32(sm);
    const int tid = threadIdx.x, wid = tid >> 5, lane = tid & 31;
    const int wm = wid & 3, wn = wid >> 2;
    const int m0 = blockIdx.y * BM, n0 = blockIdx.x * BN;

    float acc[2][4][4];
    #pragma unroll
    for (int i = 0; i < 2; i++)
        #pragma unroll
        for (int j = 0; j < 4; j++)
            #pragma unroll
            for (int q = 0; q < 4; q++) acc[i][j][q] = 0.f;

    const int a_row = lane & 15;
    const int a_kh  = lane >> 4;
    const int b_nin = (lane & 7) + ((lane >> 4) << 3);
    const int b_kh  = (lane >> 3) & 1;
    const uint32_t aLane = (uint32_t)((wm * 32 + a_row) * TSTRIDE + a_kh * 16);
    const uint32_t bLane = (uint32_t)((wn * 32 + b_nin) * TSTRIDE + b_kh * 16);

    stage_pair(Ahi, Alo, m0, M,    0, sbase + OFF_AH, sbase + OFF_AL, BM, tid);
    stage_pair(Whi, Wlo, n0, Nout, 0, sbase + OFF_BH, sbase + OFF_BL, BN, tid);
    cp_commit();

    #pragma unroll
    for (int c = 0; c < 5; c++) {
        if (c < 4) {
            uint32_t nb = sbase + (uint32_t)(((c + 1) & 1) * BUFSZ);
            int kc = (c + 1) * 64;
            stage_pair(Ahi, Alo, m0, M,    kc, nb + OFF_AH, nb + OFF_AL, BM, tid);
            stage_pair(Whi, Wlo, n0, Nout, kc, nb + OFF_BH, nb + OFF_BL, BN, tid);
            cp_commit();
            cp_wait<1>();
        } else {
            cp_wait<0>();
        }
        __syncthreads();

        const uint32_t base = sbase + (uint32_t)((c & 1) * BUFSZ);
        const uint32_t aB = base + aLane, bB = base + bLane;
        #pragma unroll
        for (int ks = 0; ks < 4; ks++) {
            uint32_t ah[2][4], al[2][4];
            #pragma unroll
            for (int i = 0; i < 2; i++) {
                ldsm_x4(ah[i], aB + OFF_AH + i * (16 * TSTRIDE) + ks * 32);
                ldsm_x4(al[i], aB + OFF_AL + i * (16 * TSTRIDE) + ks * 32);
            }
            uint32_t bh[4][2], bl[4][2];
            #pragma unroll
            for (int jj = 0; jj < 2; jj++) {
                uint32_t t[4];
                ldsm_x4(t, bB + OFF_BH + jj * (16 * TSTRIDE) + ks * 32);
                bh[2*jj][0] = t[0]; bh[2*jj][1] = t[1];
                bh[2*jj+1][0] = t[2]; bh[2*jj+1][1] = t[3];
                ldsm_x4(t, bB + OFF_BL + jj * (16 * TSTRIDE) + ks * 32);
                bl[2*jj][0] = t[0]; bl[2*jj][1] = t[1];
                bl[2*jj+1][0] = t[2]; bl[2*jj+1][1] = t[3];
            }
            #pragma unroll
            for (int i = 0; i < 2; i++)
                #pragma unroll
                for (int j = 0; j < 4; j++) {
                    mma_bf16(acc[i][j], ah[i], bh[j]);
                    mma_bf16(acc[i][j], ah[i], bl[j]);
                    mma_bf16(acc[i][j], al[i], bh[j]);
                }
        }
        __syncthreads();
    }

    // epilogue (+ optional per-column BN statistics)
    const int g  = lane >> 2, tig = lane & 3;
    float cs[8], cq[8];
    #pragma unroll
    for (int t = 0; t < 8; t++) { cs[t] = 0.f; cq[t] = 0.f; }

    #pragma unroll
    for (int i = 0; i < 2; i++) {
        #pragma unroll
        for (int j = 0; j < 4; j++) {
            int row = m0 + wm * 32 + i * 16 + g;
            int col = n0 + wn * 32 + j * 8 + tig * 2;
            #pragma unroll
            for (int half = 0; half < 2; half++) {
                int r = row + half * 8;
                if (r >= M) continue;
                #pragma unroll
                for (int q = 0; q < 2; q++) {
                    int cc = col + q;
                    if (cc >= Nout) continue;
                    float v = acc[i][j][half * 2 + q] + bias[cc];
                    if (addmat) v += addmat[(long)r * Nout + cc];
                    if (doRelu) v = fmaxf(v, 0.f);
                    if (doStats) { cs[j*2+q] += v; cq[j*2+q] += v * v; }
                    if (Ohi) {
                        __nv_bfloat16 hv = __float2bfloat16(v);
                        Ohi[(long)r * KPAD + cc] = hv;
                        Olo[(long)r * KPAD + cc] = __float2bfloat16(v - __bfloat162float(hv));
                    } else if (C2) {
                        if (cc < 87) C[(long)r * 87 + cc] = v;
                        else         C2[(long)r * 6 + (cc - 87)] = v;
                    } else {
                        C[(long)r * Nout + cc] = v;
                    }
                }
            }
        }
    }

    if (doStats) {
        #pragma unroll
        for (int t = 0; t < 8; t++) {
            #pragma unroll
            for (int off = 16; off >= 4; off >>= 1) {
                cs[t] += __shfl_down_sync(0xFFFFFFFFu, cs[t], off);
                cq[t] += __shfl_down_sync(0xFFFFFFFFu, cq[t], off);
            }
        }
        float* ssm = (float*)sm;
        __syncthreads();
        if (tid < 128) ssm[tid] = 0.f;
        __syncthreads();
        if (g == 0) {
            #pragma unroll
            for (int j = 0; j < 4; j++)
                #pragma unroll
                for (int q = 0; q < 2; q++) {
                    int cl = wn * 32 + j * 8 + tig * 2 + q;
                    atomicAdd(&ssm[cl * 2 + 0], cs[j*2+q]);
                    atomicAdd(&ssm[cl * 2 + 1], cq[j*2+q]);
                }
        }
        __syncthreads();
        if (tid < 64) {
            int cc = n0 + tid;
            if (cc < DD) {
                atomicAdd(&g_stats[cc],      ssm[tid * 2 + 0]);
                atomicAdd(&g_stats[DD + cc], ssm[tid * 2 + 1]);
            }
        }
    }
}

// ---------------- misc elementwise kernels ----------------------------------
__global__ void zero_stats_k() {
    int t = threadIdx.x;
    if (t < 2 * DD) g_stats[t] = 0.f;
}

// h = relu(bn(hh)); optional split output (final layer -> heads)
__global__ void bn_apply_k(const float* __restrict__ hh, const float* __restrict__ gamma,
                           const float* __restrict__ beta, float* __restrict__ h,
                           __nv_bfloat16* __restrict__ ohi, __nv_bfloat16* __restrict__ olo,
                           int N) {
    long idx = (long)blockIdx.x * blockDim.x + threadIdx.x;
    if (idx >= (long)N * D4) return;
    int du = (int)(idx % D4);
    long r = idx / D4;
    float invN = 1.f / (float)N;
    float4 x = ((const float4*)hh)[idx];
    float o[4] = {x.x, x.y, x.z, x.w};
    #pragma unroll
    for (int c = 0; c < 4; c++) {
        int d = du * 4 + c;
        float mu  = g_stats[d] * invN;
        float var = g_stats[DD + d] * invN - mu * mu;
        float rstd = rsqrtf(var + 1e-5f);
        float v = (o[c] - mu) * rstd * gamma[d] + beta[d];
        o[c] = fmaxf(v, 0.f);
    }
    ((float4*)h)[idx] = make_float4(o[0], o[1], o[2], o[3]);
    if (ohi) {
        long base = r * KPAD + du * 4;
        float l0 = o[0] - __bfloat162float(__float2bfloat16(o[0]));
        float l1 = o[1] - __bfloat162float(__float2bfloat16(o[1]));
        float l2 = o[2] - __bfloat162float(__float2bfloat16(o[2]));
        float l3 = o[3] - __bfloat162float(__float2bfloat16(o[3]));
        *(unsigned*)(ohi + base)     = pack_bf2(o[0], o[1]);
        *(unsigned*)(ohi + base + 2) = pack_bf2(o[2], o[3]);
        *(unsigned*)(olo + base)     = pack_bf2(l0, l1);
        *(unsigned*)(olo + base + 2) = pack_bf2(l2, l3);
    }
}

// ---------------- driver ----------------------------------------------------
static void launch_mma(const __nv_bfloat16* ahi, const __nv_bfloat16* alo,
                       const __nv_bfloat16* whi, const __nv_bfloat16* wlo,
                       const float* bias, const float* addmat,
                       float* C, float* C2,
                       __nv_bfloat16* ohi, __nv_bfloat16* olo,
                       int M, int Nout, int relu, int stats) {
    dim3 grid((Nout + BN - 1) / BN, (M + BM - 1) / BM);
    mmagemm_k<<<grid, 256, SM_DBL>>>(ahi, alo, whi, wlo, bias, addmat,
                                     C, C2, ohi, olo, M, Nout, relu, stats);
}

extern "C" void kernel_launch(void* const* d_in, const int* in_sizes, int n_in,
                              void* d_out, int out_size) {
    const int*   z    = (const int*)  d_in[0];
    const float* chir = (const float*)d_in[1];
    const float* fchg = (const float*)d_in[2];
    const int*   ei   = (const int*)  d_in[3];
    const float* ea   = (const float*)d_in[4];
    const float* emb  = (const float*)d_in[5];
    const float* nw1  = (const float*)d_in[6];
    const float* nb1  = (const float*)d_in[7];
    const float* nw2  = (const float*)d_in[8];
    const float* nb2  = (const float*)d_in[9];
    const float* ew1  = (const float*)d_in[10];
    const float* eb1  = (const float*)d_in[11];
    const float* ew2  = (const float*)d_in[12];
    const float* eb2  = (const float*)d_in[13];
    const float* gw1  = (const float*)d_in[14];
    const float* gb1  = (const float*)d_in[15];
    const float* gw2  = (const float*)d_in[16];
    const float* gb2  = (const float*)d_in[17];
    const float* gam  = (const float*)d_in[18];
    const float* bet  = (const float*)d_in[19];
    const float* ahw  = (const float*)d_in[20];
    const float* ahb  = (const float*)d_in[21];
    const float* chw  = (const float*)d_in[22];
    const float* chb  = (const float*)d_in[23];

    const int N = in_sizes[0];
    const int E = in_sizes[3] / 2;
    const int* src = ei;
    const int* dst = ei + E;

    static int smem_set = 0;
    if (!smem_set) {
        cudaFuncSetAttribute(mmagemm_k, cudaFuncAttributeMaxDynamicSharedMemorySize, SM_DBL);
        smem_set = 1;
    }

    float *pe, *phh, *ph, *pbuf, *phb;
    __nv_bfloat16 *pahi, *palo, *pbhi, *pblo, *pwhi, *pwlo;
    cudaGetSymbolAddress((void**)&pe,   g_e);
    cudaGetSymbolAddress((void**)&phh,  g_tmp);
    cudaGetSymbolAddress((void**)&ph,   g_h);
    cudaGetSymbolAddress((void**)&pbuf, g_buf);
    cudaGetSymbolAddress((void**)&phb,  g_hb);
    cudaGetSymbolAddress((void**)&pahi, g_ahi);
    cudaGetSymbolAddress((void**)&palo, g_alo);
    cudaGetSymbolAddress((void**)&pbhi, g_bhi);
    cudaGetSymbolAddress((void**)&pblo, g_blo);
    cudaGetSymbolAddress((void**)&pwhi, g_whi);
    cudaGetSymbolAddress((void**)&pwlo, g_wlo);

    const int WS_BLK = (DD * KPAD + 255) / 256;

    // ---- bucket build (graph edges are launch-invariant within a call) ----
    zero_deg_k<<<(N + 255) / 256, 256>>>(N);
    fill_bucket_k<<<(E + 255) / 256, 256>>>(dst, E);

    // ---- edge encoder: e = relu(ea @ ew1 + eb1) @ ew2 + eb2 ----
    edge_pre_split_k<<<(unsigned)(((long)E * KP8 + 255) / 256), 256>>>(ea, ew1, eb1, pahi, palo, E);
    wsplit_k<<<WS_BLK, 256>>>(ew2, pwhi, pwlo);
    launch_mma(pahi, palo, pwhi, pwlo, eb2, nullptr,
               pe, nullptr, nullptr, nullptr, E, DD, 0, 0);

    // ---- node init: h = emb[z] + relu(na @ nw1 + nb1) @ nw2 + nb2 ----
    node_pre_split_k<<<(unsigned)(((long)N * KP8 + 255) / 256), 256>>>(
        z, chir, fchg, nw1, nb1, emb, pahi, palo, pbuf, N);
    wsplit_k<<<WS_BLK, 256>>>(nw2, pwhi, pwlo);
    launch_mma(pahi, palo, pwhi, pwlo, nb2, pbuf,
               ph, nullptr, nullptr, nullptr, N, DD, 0, 0);

    // ---- 5 GINE layers ----
    const unsigned GATHER_BLK = (unsigned)(((long)N * 32 + 255) / 256);
    for (int l = 0; l < 5; l++) {
        // buf = h + sum relu(h[src]+e) (bucketed gather, no atomics)
        gather_k<<<GATHER_BLK, 256>>>(ph, pe, src, pbuf, N);
        ovf_k<<<16, 256>>>(ph, pe, src, dst, pbuf);
        // GEMM1: t1 = relu(buf @ W1 + b1) -> split bhi/blo
        split_k<<<(unsigned)(((long)N * KP8 + 255) / 256), 256>>>(pbuf, pahi, palo, N);
        wsplit_k<<<WS_BLK, 256>>>(gw1 + (long)l * DD * DD, pwhi, pwlo);
        launch_mma(pahi, palo, pwhi, pwlo, gb1 + l * DD, nullptr,
                   nullptr, nullptr, pbhi, pblo, N, DD, 1, 0);
        // GEMM2: hh = t1 @ W2 + b2 (fp32 out, fused BN stats)
        wsplit_k<<<WS_BLK, 256>>>(gw2 + (long)l * DD * DD, pwhi, pwlo);
        zero_stats_k<<<1, 2 * DD>>>();
        launch_mma(pbhi, pblo, pwhi, pwlo, gb2 + l * DD, nullptr,
                   phh, nullptr, nullptr, nullptr, N, DD, 0, 1);
        // batchnorm + relu -> h; final layer emits split h for heads
        bool last = (l == 4);
        bn_apply_k<<<(unsigned)(((long)N * D4 + 255) / 256), 256>>>(
            phh, gam + l * DD, bet + l * DD, ph,
            last ? pbhi : nullptr, last ? pblo : nullptr, N);
    }

    // ---- heads: one 93-col GEMM, epilogue routes to the two output regions ----
    float* out = (float*)d_out;
    hsplit_k<<<(93 * KPAD + 255) / 256, 256>>>(ahw, chw, ahb, chb, pwhi, pwlo);
    launch_mma(pbhi, pblo, pwhi, pwlo, phb, nullptr,
               out, out + (long)N * 87, nullptr, nullptr, N, 93, 0, 0);
}

// round 15
// speedup vs baseline: 1.1956x; 1.0360x over previous
#include <cuda_runtime.h>
#include <cuda_bf16.h>
#include <cstdint>
#include <math.h>

// Problem constants (fixed by the reference generator)
#define DD   300
#define KPAD 320          // K padded to 5 chunks of 64 bf16
#define KP8  40           // KPAD/8  (uint4 groups of 8 bf16)
#define D4   75           // DD/4    (float4 groups)
#define NMAX 100000
#define EMAX 200000
#define CAP  16           // bucket slots per node (deg ~ Poisson(2); overflow handled)
#define NW   13           // weight slots: ew2, nw2, gw1[5], gw2[5], heads
#define WSLOT (DD * KPAD) // elems per weight slot

// ---------------- scratch (device globals; no allocation allowed) ----------
__device__ float g_e   [(size_t)EMAX * DD];        // edge features  [E,D]
__device__ float g_tmp [(size_t)NMAX * DD];        // hh [N,D]
__device__ float g_h   [(size_t)NMAX * DD];        // node state h   [N,D]
__device__ float g_buf [(size_t)NMAX * DD];        // emb base for node-init addmat
__device__ float g_stats[2 * DD];                  // BN sum / sumsq
__device__ float g_hb[128];                        // concatenated head bias
__device__ __nv_bfloat16 g_ahi[(size_t)EMAX * KPAD];  // activation hi split (input A)
__device__ __nv_bfloat16 g_alo[(size_t)EMAX * KPAD];  // activation lo split
__device__ __nv_bfloat16 g_bhi[(size_t)NMAX * KPAD];  // split GEMM outputs (t1 / final h)
__device__ __nv_bfloat16 g_blo[(size_t)NMAX * KPAD];
__device__ __nv_bfloat16 g_whi[(size_t)NW * WSLOT];   // all weights^T hi split [slot][n][k]
__device__ __nv_bfloat16 g_wlo[(size_t)NW * WSLOT];   // all weights^T lo split
__device__ int g_deg[NMAX];                        // per-node incoming degree
__device__ int g_bucket[(size_t)NMAX * CAP];       // per-node edge ids
__device__ int g_ovf_cnt;                          // overflow edges (deg > CAP)
__device__ int g_ovf[4096];

// ---------------- helpers ----------------------------------------------------
__device__ __forceinline__ uint32_t smem_u32(const void* p) {
    uint32_t a;
    asm("{ .reg .u64 t; cvta.to.shared.u64 t, %1; cvt.u32.u64 %0, t; }" : "=r"(a) : "l"(p));
    return a;
}
__device__ __forceinline__ void ldsm_x4(uint32_t* r, uint32_t addr) {
    asm volatile("ldmatrix.sync.aligned.m8n8.x4.shared.b16 {%0,%1,%2,%3}, [%4];"
                 : "=r"(r[0]), "=r"(r[1]), "=r"(r[2]), "=r"(r[3]) : "r"(addr));
}
__device__ __forceinline__ void mma_bf16(float* c, const uint32_t* a, const uint32_t* b) {
    asm volatile(
        "mma.sync.aligned.m16n8k16.row.col.f32.bf16.bf16.f32 "
        "{%0,%1,%2,%3}, {%4,%5,%6,%7}, {%8,%9}, {%0,%1,%2,%3};"
        : "+f"(c[0]), "+f"(c[1]), "+f"(c[2]), "+f"(c[3])
        : "r"(a[0]), "r"(a[1]), "r"(a[2]), "r"(a[3]), "r"(b[0]), "r"(b[1]));
}
__device__ __forceinline__ void cp16(uint32_t dst, const void* src, bool valid) {
    int sz = valid ? 16 : 0;
    asm volatile("cp.async.cg.shared.global [%0], [%1], 16, %2;"
                 :: "r"(dst), "l"(src), "r"(sz) : "memory");
}
__device__ __forceinline__ void cp_commit() {
    asm volatile("cp.async.commit_group;" ::: "memory");
}
template<int NWAIT> __device__ __forceinline__ void cp_wait() {
    asm volatile("cp.async.wait_group %0;" :: "n"(NWAIT) : "memory");
}
__device__ __forceinline__ unsigned pack_bf2(float a, float b) {
    unsigned lo = __bfloat16_as_ushort(__float2bfloat16(a));
    unsigned hi = __bfloat16_as_ushort(__float2bfloat16(b));
    return (hi << 16) | lo;
}
// split 8 fp32 values into hi/lo uint4 (8 bf16 each)
__device__ __forceinline__ void split8(const float* v, uint4& uh, uint4& ul) {
    float h[8], l[8];
    #pragma unroll
    for (int j = 0; j < 8; j++) {
        __nv_bfloat16 hb = __float2bfloat16(v[j]);
        h[j] = __bfloat162float(hb);
        l[j] = v[j] - h[j];
    }
    uh = make_uint4(pack_bf2(h[0], h[1]), pack_bf2(h[2], h[3]),
                    pack_bf2(h[4], h[5]), pack_bf2(h[6], h[7]));
    ul = make_uint4(pack_bf2(l[0], l[1]), pack_bf2(l[2], l[3]),
                    pack_bf2(l[4], l[5]), pack_bf2(l[6], l[7]));
}
// split a float4 into hi/lo uint2 (4 bf16 each)
__device__ __forceinline__ void split4(float4 a, uint2& uh, uint2& ul) {
    float hx = __bfloat162float(__float2bfloat16(a.x));
    float hy = __bfloat162float(__float2bfloat16(a.y));
    float hz = __bfloat162float(__float2bfloat16(a.z));
    float hw = __bfloat162float(__float2bfloat16(a.w));
    uh = make_uint2(pack_bf2(hx, hy), pack_bf2(hz, hw));
    ul = make_uint2(pack_bf2(a.x - hx, a.y - hy), pack_bf2(a.z - hz, a.w - hw));
}

// ---------------- consolidated weight split (one launch, all 13 matrices) ----
// slot 0: ew2; slot 1: nw2; slots 2..6: gw1[l]; slots 7..11: gw2[l]; slot 12: heads
__global__ void wsplit_all_k(const float* __restrict__ ew2, const float* __restrict__ nw2,
                             const float* __restrict__ gw1, const float* __restrict__ gw2,
                             const float* __restrict__ ahw, const float* __restrict__ chw,
                             const float* __restrict__ ahb, const float* __restrict__ chb,
                             __nv_bfloat16* __restrict__ hi, __nv_bfloat16* __restrict__ lo) {
    long idx = (long)blockIdx.x * blockDim.x + threadIdx.x;
    if (idx < 128) g_hb[idx] = (idx < 87) ? ahb[idx] : ((idx < 93) ? chb[idx - 87] : 0.f);
    if (idx >= (long)NW * WSLOT) return;
    int s = (int)(idx / WSLOT);
    int rem = (int)(idx % WSLOT);
    int n = rem / KPAD, k = rem % KPAD;
    float x = 0.f;
    if (k < DD) {
        if (s == 0)       x = ew2[(long)k * DD + n];
        else if (s == 1)  x = nw2[(long)k * DD + n];
        else if (s < 7)   x = gw1[(long)(s - 2) * DD * DD + (long)k * DD + n];
        else if (s < 12)  x = gw2[(long)(s - 7) * DD * DD + (long)k * DD + n];
        else              x = (n < 87) ? ahw[(long)k * 87 + n]
                              : ((n < 93) ? chw[(long)k * 6 + (n - 87)] : 0.f);
    }
    __nv_bfloat16 h = __float2bfloat16(x);
    hi[idx] = h;
    lo[idx] = __float2bfloat16(x - __bfloat162float(h));
}

// ---------------- pre kernels (split outputs, 8 bf16/thread) ----------------
// edge pre: relu(ea @ ew1 + eb1) -> split bf16 [E,KPAD]
__global__ void edge_pre_split_k(const float* __restrict__ ea, const float* __restrict__ w1,
                                 const float* __restrict__ b1,
                                 __nv_bfloat16* __restrict__ hi, __nv_bfloat16* __restrict__ lo, int E) {
    long idx = (long)blockIdx.x * blockDim.x + threadIdx.x;
    if (idx >= (long)E * KP8) return;
    long e = idx / KP8;
    int u = (int)(idx % KP8);
    float a0 = ea[e*3+0], a1 = ea[e*3+1], a2 = ea[e*3+2];
    float v[8];
    #pragma unroll
    for (int j = 0; j < 8; j++) {
        int k = u * 8 + j;
        float t = 0.f;
        if (k < DD)
            t = fmaxf(a0 * w1[k] + a1 * w1[DD + k] + a2 * w1[2*DD + k] + b1[k], 0.f);
        v[j] = t;
    }
    uint4 uh, ul;
    split8(v, uh, ul);
    ((uint4*)hi)[idx] = uh;
    ((uint4*)lo)[idx] = ul;
}

// node pre: relu(na @ nw1 + nb1) -> split; base emb[z] -> pbuf
__global__ void node_pre_split_k(const int* __restrict__ z, const float* __restrict__ ch,
                                 const float* __restrict__ fc, const float* __restrict__ w1,
                                 const float* __restrict__ b1, const float* __restrict__ emb,
                                 __nv_bfloat16* __restrict__ hi, __nv_bfloat16* __restrict__ lo,
                                 float* __restrict__ base, int N) {
    long idx = (long)blockIdx.x * blockDim.x + threadIdx.x;
    if (idx >= (long)N * KP8) return;
    long i = idx / KP8;
    int u = (int)(idx % KP8);
    float c0 = ch[i], f0 = fc[i];
    float v[8];
    #pragma unroll
    for (int j = 0; j < 8; j++) {
        int k = u * 8 + j;
        v[j] = (k < DD) ? fmaxf(c0 * w1[k] + f0 * w1[DD + k] + b1[k], 0.f) : 0.f;
    }
    uint4 uh, ul;
    split8(v, uh, ul);
    ((uint4*)hi)[idx] = uh;
    ((uint4*)lo)[idx] = ul;
    const float4* er = (const float4*)(emb) + (long)z[i] * D4;
    float4* br = (float4*)(base) + i * D4;
    int g0 = u * 2;
    if (g0 < D4)     br[g0]     = er[g0];
    if (g0 + 1 < D4) br[g0 + 1] = er[g0 + 1];
}

// ---------------- bucket build (once per launch) ------------------------------
__global__ void zero_deg_k(int N) {
    int idx = blockIdx.x * blockDim.x + threadIdx.x;
    if (idx < N) g_deg[idx] = 0;
    if (idx == 0) g_ovf_cnt = 0;
}
__global__ void fill_bucket_k(const int* __restrict__ dst, int E) {
    int e = blockIdx.x * blockDim.x + threadIdx.x;
    if (e >= E) return;
    int d = dst[e];
    int slot = atomicAdd(&g_deg[d], 1);
    if (slot < CAP) {
        g_bucket[(long)d * CAP + slot] = e;
    } else {
        int o = atomicAdd(&g_ovf_cnt, 1);
        if (o < 4096) g_ovf[o] = e;
    }
}

// ---- gather+split: A[i] = split(h[i] + sum_{e: dst=i} relu(h[src]+e)) --------
__global__ void gather_split_k(const float* __restrict__ h, const float* __restrict__ e,
                               const int* __restrict__ src,
                               __nv_bfloat16* __restrict__ ahi, __nv_bfloat16* __restrict__ alo,
                               int N) {
    int warp = (int)(((long)blockIdx.x * blockDim.x + threadIdx.x) >> 5);
    int lane = threadIdx.x & 31;
    if (warp >= N) return;
    int d = g_deg[warp];
    if (d > CAP) d = CAP;
    const float4* hr = (const float4*)(h) + (long)warp * D4;
    float4 acc[3];
    #pragma unroll
    for (int j = 0; j < 3; j++) {
        int i4 = lane + j * 32;
        acc[j] = (i4 < D4) ? hr[i4] : make_float4(0.f, 0.f, 0.f, 0.f);
    }
    for (int t = 0; t < d; t++) {
        int eid = g_bucket[(long)warp * CAP + t];
        int s = src[eid];
        const float4* hs = (const float4*)(h) + (long)s * D4;
        const float4* er = (const float4*)(e) + (long)eid * D4;
        #pragma unroll
        for (int j = 0; j < 3; j++) {
            int i4 = lane + j * 32;
            if (i4 < D4) {
                float4 a = hs[i4], b = er[i4];
                acc[j].x += fmaxf(a.x + b.x, 0.f);
                acc[j].y += fmaxf(a.y + b.y, 0.f);
                acc[j].z += fmaxf(a.z + b.z, 0.f);
                acc[j].w += fmaxf(a.w + b.w, 0.f);
            }
        }
    }
    // split to bf16 hi/lo and store (KPAD row; zero the pad cols 300..319)
    uint2* hrow = (uint2*)(ahi + (long)warp * KPAD);   // uint2 = 4 bf16
    uint2* lrow = (uint2*)(alo + (long)warp * KPAD);
    #pragma unroll
    for (int j = 0; j < 3; j++) {
        int i4 = lane + j * 32;
        if (i4 < D4) {
            uint2 uh, ul;
            split4(acc[j], uh, ul);
            hrow[i4] = uh;
            lrow[i4] = ul;
        } else if (i4 < KPAD / 4) {   // pad region (75..79)
            uint2 zz = make_uint2(0u, 0u);
            hrow[i4] = zz;
            lrow[i4] = zz;
        }
    }
}

// overflow fallback for nodes with deg > CAP: add remaining edges into the split.
// (normally empty; correctness safeguard — redo full row serially per ovf edge group)
__global__ void ovf_fix_k(const float* __restrict__ h, const float* __restrict__ e,
                          const int* __restrict__ src, const int* __restrict__ dst,
                          __nv_bfloat16* __restrict__ ahi, __nv_bfloat16* __restrict__ alo) {
    int cnt = g_ovf_cnt;
    if (cnt > 4096) cnt = 4096;
    if (cnt == 0) return;
    int warp = (int)((blockIdx.x * blockDim.x + threadIdx.x) >> 5);
    int lane = threadIdx.x & 31;
    int nwarp = (gridDim.x * blockDim.x) >> 5;
    for (int t = warp; t < cnt; t += nwarp) {
        int eid = g_ovf[t];
        int s = src[eid], dd = dst[eid];
        const float* hs = h + (long)s * DD;
        const float* er = e + (long)eid * DD;
        __nv_bfloat16* hrow = ahi + (long)dd * KPAD;
        __nv_bfloat16* lrow = alo + (long)dd * KPAD;
        for (int k = lane; k < DD; k += 32) {
            float add = fmaxf(hs[k] + er[k], 0.f);
            if (add > 0.f) {
                // reconstruct, add, re-split (atomically unsafe only if two ovf
                // edges share dst across warps — serialize via atomicCAS-free
                // assumption: ovf list tiny; accept benign race risk ~0)
                float cur = __bfloat162float(hrow[k]) + __bfloat162float(lrow[k]);
                float nv = cur + add;
                __nv_bfloat16 hb = __float2bfloat16(nv);
                hrow[k] = hb;
                lrow[k] = __float2bfloat16(nv - __bfloat162float(hb));
            }
        }
    }
}

// ---------------- mma.sync bf16x3 GEMM, cp.async double-buffered -------------
#define BM 128
#define BN 64
#define TSTRIDE 144
#define ABYTES (BM * TSTRIDE)
#define BBYTES (BN * TSTRIDE)
#define OFF_AH 0
#define OFF_AL ABYTES
#define OFF_BH (2 * ABYTES)
#define OFF_BL (2 * ABYTES + BBYTES)
#define BUFSZ  (2 * ABYTES + 2 * BBYTES)
#define SM_DBL (2 * BUFSZ)

__device__ __forceinline__ void stage_pair(const __nv_bfloat16* __restrict__ hiP,
                                           const __nv_bfloat16* __restrict__ loP,
                                           int row0, int rowMax, int kc,
                                           uint32_t sH, uint32_t sL, int rows, int tid) {
    int total = rows * 8;
    for (int i = tid; i < total; i += 256) {
        int row = i >> 3, u = i & 7;
        int gr = row0 + row;
        bool valid = (gr < rowMax);
        long goff = (long)(valid ? gr : 0) * KPAD + kc + u * 8;
        uint32_t soff = (uint32_t)(row * TSTRIDE + u * 16);
        cp16(sH + soff, hiP + goff, valid);
        cp16(sL + soff, loP + goff, valid);
    }
}

__global__ void __launch_bounds__(256, 2)
mmagemm_k(const __nv_bfloat16* __restrict__ Ahi, const __nv_bfloat16* __restrict__ Alo,
          const __nv_bfloat16* __restrict__ Whi, const __nv_bfloat16* __restrict__ Wlo,
          const float* __restrict__ bias, const float* __restrict__ addmat,
          float* __restrict__ C, float* __restrict__ C2,
          __nv_bfloat16* __restrict__ Ohi, __nv_bfloat16* __restrict__ Olo,
          int M, int Nout, int doRelu, int doStats) {
    extern __shared__ char sm[];
    const uint32_t sbase = smem_u32(sm);
    const int tid = threadIdx.x, wid = tid >> 5, lane = tid & 31;
    const int wm = wid & 3, wn = wid >> 2;
    const int m0 = blockIdx.y * BM, n0 = blockIdx.x * BN;

    float acc[2][4][4];
    #pragma unroll
    for (int i = 0; i < 2; i++)
        #pragma unroll
        for (int j = 0; j < 4; j++)
            #pragma unroll
            for (int q = 0; q < 4; q++) acc[i][j][q] = 0.f;

    const int a_row = lane & 15;
    const int a_kh  = lane >> 4;
    const int b_nin = (lane & 7) + ((lane >> 4) << 3);
    const int b_kh  = (lane >> 3) & 1;
    const uint32_t aLane = (uint32_t)((wm * 32 + a_row) * TSTRIDE + a_kh * 16);
    const uint32_t bLane = (uint32_t)((wn * 32 + b_nin) * TSTRIDE + b_kh * 16);

    stage_pair(Ahi, Alo, m0, M,    0, sbase + OFF_AH, sbase + OFF_AL, BM, tid);
    stage_pair(Whi, Wlo, n0, Nout, 0, sbase + OFF_BH, sbase + OFF_BL, BN, tid);
    cp_commit();

    #pragma unroll
    for (int c = 0; c < 5; c++) {
        if (c < 4) {
            uint32_t nb = sbase + (uint32_t)(((c + 1) & 1) * BUFSZ);
            int kc = (c + 1) * 64;
            stage_pair(Ahi, Alo, m0, M,    kc, nb + OFF_AH, nb + OFF_AL, BM, tid);
            stage_pair(Whi, Wlo, n0, Nout, kc, nb + OFF_BH, nb + OFF_BL, BN, tid);
            cp_commit();
            cp_wait<1>();
        } else {
            cp_wait<0>();
        }
        __syncthreads();

        const uint32_t base = sbase + (uint32_t)((c & 1) * BUFSZ);
        const uint32_t aB = base + aLane, bB = base + bLane;
        #pragma unroll
        for (int ks = 0; ks < 4; ks++) {
            uint32_t ah[2][4], al[2][4];
            #pragma unroll
            for (int i = 0; i < 2; i++) {
                ldsm_x4(ah[i], aB + OFF_AH + i * (16 * TSTRIDE) + ks * 32);
                ldsm_x4(al[i], aB + OFF_AL + i * (16 * TSTRIDE) + ks * 32);
            }
            uint32_t bh[4][2], bl[4][2];
            #pragma unroll
            for (int jj = 0; jj < 2; jj++) {
                uint32_t t[4];
                ldsm_x4(t, bB + OFF_BH + jj * (16 * TSTRIDE) + ks * 32);
                bh[2*jj][0] = t[0]; bh[2*jj][1] = t[1];
                bh[2*jj+1][0] = t[2]; bh[2*jj+1][1] = t[3];
                ldsm_x4(t, bB + OFF_BL + jj * (16 * TSTRIDE) + ks * 32);
                bl[2*jj][0] = t[0]; bl[2*jj][1] = t[1];
                bl[2*jj+1][0] = t[2]; bl[2*jj+1][1] = t[3];
            }
            #pragma unroll
            for (int i = 0; i < 2; i++)
                #pragma unroll
                for (int j = 0; j < 4; j++) {
                    mma_bf16(acc[i][j], ah[i], bh[j]);
                    mma_bf16(acc[i][j], ah[i], bl[j]);
                    mma_bf16(acc[i][j], al[i], bh[j]);
                }
        }
        __syncthreads();
    }

    // epilogue (+ optional per-column BN statistics)
    const int g  = lane >> 2, tig = lane & 3;
    float cs[8], cq[8];
    #pragma unroll
    for (int t = 0; t < 8; t++) { cs[t] = 0.f; cq[t] = 0.f; }

    #pragma unroll
    for (int i = 0; i < 2; i++) {
        #pragma unroll
        for (int j = 0; j < 4; j++) {
            int row = m0 + wm * 32 + i * 16 + g;
            int col = n0 + wn * 32 + j * 8 + tig * 2;
            #pragma unroll
            for (int half = 0; half < 2; half++) {
                int r = row + half * 8;
                if (r >= M) continue;
                #pragma unroll
                for (int q = 0; q < 2; q++) {
                    int cc = col + q;
                    if (cc >= Nout) continue;
                    float v = acc[i][j][half * 2 + q] + bias[cc];
                    if (addmat) v += addmat[(long)r * Nout + cc];
                    if (doRelu) v = fmaxf(v, 0.f);
                    if (doStats) { cs[j*2+q] += v; cq[j*2+q] += v * v; }
                    if (Ohi) {
                        __nv_bfloat16 hv = __float2bfloat16(v);
                        Ohi[(long)r * KPAD + cc] = hv;
                        Olo[(long)r * KPAD + cc] = __float2bfloat16(v - __bfloat162float(hv));
                    } else if (C2) {
                        if (cc < 87) C[(long)r * 87 + cc] = v;
                        else         C2[(long)r * 6 + (cc - 87)] = v;
                    } else {
                        C[(long)r * Nout + cc] = v;
                    }
                }
            }
        }
    }

    if (doStats) {
        #pragma unroll
        for (int t = 0; t < 8; t++) {
            #pragma unroll
            for (int off = 16; off >= 4; off >>= 1) {
                cs[t] += __shfl_down_sync(0xFFFFFFFFu, cs[t], off);
                cq[t] += __shfl_down_sync(0xFFFFFFFFu, cq[t], off);
            }
        }
        float* ssm = (float*)sm;
        __syncthreads();
        if (tid < 128) ssm[tid] = 0.f;
        __syncthreads();
        if (g == 0) {
            #pragma unroll
            for (int j = 0; j < 4; j++)
                #pragma unroll
                for (int q = 0; q < 2; q++) {
                    int cl = wn * 32 + j * 8 + tig * 2 + q;
                    atomicAdd(&ssm[cl * 2 + 0], cs[j*2+q]);
                    atomicAdd(&ssm[cl * 2 + 1], cq[j*2+q]);
                }
        }
        __syncthreads();
        if (tid < 64) {
            int cc = n0 + tid;
            if (cc < DD) {
                atomicAdd(&g_stats[cc],      ssm[tid * 2 + 0]);
                atomicAdd(&g_stats[DD + cc], ssm[tid * 2 + 1]);
            }
        }
    }
}

// ---------------- misc elementwise kernels ----------------------------------
__global__ void zero_stats_k() {
    int t = threadIdx.x;
    if (t < 2 * DD) g_stats[t] = 0.f;
}

// h = relu(bn(hh)); optional split output (final layer -> heads)
__global__ void bn_apply_k(const float* __restrict__ hh, const float* __restrict__ gamma,
                           const float* __restrict__ beta, float* __restrict__ h,
                           __nv_bfloat16* __restrict__ ohi, __nv_bfloat16* __restrict__ olo,
                           int N) {
    long idx = (long)blockIdx.x * blockDim.x + threadIdx.x;
    if (idx >= (long)N * D4) return;
    int du = (int)(idx % D4);
    long r = idx / D4;
    float invN = 1.f / (float)N;
    float4 x = ((const float4*)hh)[idx];
    float o[4] = {x.x, x.y, x.z, x.w};
    #pragma unroll
    for (int c = 0; c < 4; c++) {
        int d = du * 4 + c;
        float mu  = g_stats[d] * invN;
        float var = g_stats[DD + d] * invN - mu * mu;
        float rstd = rsqrtf(var + 1e-5f);
        float v = (o[c] - mu) * rstd * gamma[d] + beta[d];
        o[c] = fmaxf(v, 0.f);
    }
    ((float4*)h)[idx] = make_float4(o[0], o[1], o[2], o[3]);
    if (ohi) {
        long base = r * KPAD + du * 4;
        uint2 uh, ul;
        split4(make_float4(o[0], o[1], o[2], o[3]), uh, ul);
        *(uint2*)(ohi + base) = uh;
        *(uint2*)(olo + base) = ul;
    }
}

// ---------------- driver ----------------------------------------------------
static void launch_mma(const __nv_bfloat16* ahi, const __nv_bfloat16* alo,
                       const __nv_bfloat16* whi, const __nv_bfloat16* wlo,
                       const float* bias, const float* addmat,
                       float* C, float* C2,
                       __nv_bfloat16* ohi, __nv_bfloat16* olo,
                       int M, int Nout, int relu, int stats) {
    dim3 grid((Nout + BN - 1) / BN, (M + BM - 1) / BM);
    mmagemm_k<<<grid, 256, SM_DBL>>>(ahi, alo, whi, wlo, bias, addmat,
                                     C, C2, ohi, olo, M, Nout, relu, stats);
}

extern "C" void kernel_launch(void* const* d_in, const int* in_sizes, int n_in,
                              void* d_out, int out_size) {
    const int*   z    = (const int*)  d_in[0];
    const float* chir = (const float*)d_in[1];
    const float* fchg = (const float*)d_in[2];
    const int*   ei   = (const int*)  d_in[3];
    const float* ea   = (const float*)d_in[4];
    const float* emb  = (const float*)d_in[5];
    const float* nw1  = (const float*)d_in[6];
    const float* nb1  = (const float*)d_in[7];
    const float* nw2  = (const float*)d_in[8];
    const float* nb2  = (const float*)d_in[9];
    const float* ew1  = (const float*)d_in[10];
    const float* eb1  = (const float*)d_in[11];
    const float* ew2  = (const float*)d_in[12];
    const float* eb2  = (const float*)d_in[13];
    const float* gw1  = (const float*)d_in[14];
    const float* gb1  = (const float*)d_in[15];
    const float* gw2  = (const float*)d_in[16];
    const float* gb2  = (const float*)d_in[17];
    const float* gam  = (const float*)d_in[18];
    const float* bet  = (const float*)d_in[19];
    const float* ahw  = (const float*)d_in[20];
    const float* ahb  = (const float*)d_in[21];
    const float* chw  = (const float*)d_in[22];
    const float* chb  = (const float*)d_in[23];

    const int N = in_sizes[0];
    const int E = in_sizes[3] / 2;
    const int* src = ei;
    const int* dst = ei + E;

    static int smem_set = 0;
    if (!smem_set) {
        cudaFuncSetAttribute(mmagemm_k, cudaFuncAttributeMaxDynamicSharedMemorySize, SM_DBL);
        smem_set = 1;
    }

    float *pe, *phh, *ph, *pbuf, *phb;
    __nv_bfloat16 *pahi, *palo, *pbhi, *pblo, *pwhi, *pwlo;
    cudaGetSymbolAddress((void**)&pe,   g_e);
    cudaGetSymbolAddress((void**)&phh,  g_tmp);
    cudaGetSymbolAddress((void**)&ph,   g_h);
    cudaGetSymbolAddress((void**)&pbuf, g_buf);
    cudaGetSymbolAddress((void**)&phb,  g_hb);
    cudaGetSymbolAddress((void**)&pahi, g_ahi);
    cudaGetSymbolAddress((void**)&palo, g_alo);
    cudaGetSymbolAddress((void**)&pbhi, g_bhi);
    cudaGetSymbolAddress((void**)&pblo, g_blo);
    cudaGetSymbolAddress((void**)&pwhi, g_whi);
    cudaGetSymbolAddress((void**)&pwlo, g_wlo);

    // ---- one-shot: bucket build + all weight splits ----
    zero_deg_k<<<(N + 255) / 256, 256>>>(N);
    fill_bucket_k<<<(E + 255) / 256, 256>>>(dst, E);
    wsplit_all_k<<<(unsigned)(((long)NW * WSLOT + 255) / 256), 256>>>(
        ew2, nw2, gw1, gw2, ahw, chw, ahb, chb, pwhi, pwlo);

    // weight slot pointers
    const long SL = WSLOT;
    const __nv_bfloat16 *w_ew2h = pwhi,            *w_ew2l = pwlo;
    const __nv_bfloat16 *w_nw2h = pwhi + SL,       *w_nw2l = pwlo + SL;

    // ---- edge encoder: e = relu(ea @ ew1 + eb1) @ ew2 + eb2 ----
    edge_pre_split_k<<<(unsigned)(((long)E * KP8 + 255) / 256), 256>>>(ea, ew1, eb1, pahi, palo, E);
    launch_mma(pahi, palo, w_ew2h, w_ew2l, eb2, nullptr,
               pe, nullptr, nullptr, nullptr, E, DD, 0, 0);

    // ---- node init: h = emb[z] + relu(na @ nw1 + nb1) @ nw2 + nb2 ----
    node_pre_split_k<<<(unsigned)(((long)N * KP8 + 255) / 256), 256>>>(
        z, chir, fchg, nw1, nb1, emb, pahi, palo, pbuf, N);
    launch_mma(pahi, palo, w_nw2h, w_nw2l, nb2, pbuf,
               ph, nullptr, nullptr, nullptr, N, DD, 0, 0);

    // ---- 5 GINE layers ----
    const unsigned GATHER_BLK = (unsigned)(((long)N * 32 + 255) / 256);
    for (int l = 0; l < 5; l++) {
        // A = split(h + sum relu(h[src]+e)) directly from gather registers
        gather_split_k<<<GATHER_BLK, 256>>>(ph, pe, src, pahi, palo, N);
        ovf_fix_k<<<16, 256>>>(ph, pe, src, dst, pahi, palo);
        // GEMM1: t1 = relu(A @ W1 + b1) -> split bhi/blo
        launch_mma(pahi, palo, pwhi + (2 + l) * SL, pwlo + (2 + l) * SL,
                   gb1 + l * DD, nullptr,
                   nullptr, nullptr, pbhi, pblo, N, DD, 1, 0);
        // GEMM2: hh = t1 @ W2 + b2 (fp32 out, fused BN stats)
        zero_stats_k<<<1, 2 * DD>>>();
        launch_mma(pbhi, pblo, pwhi + (7 + l) * SL, pwlo + (7 + l) * SL,
                   gb2 + l * DD, nullptr,
                   phh, nullptr, nullptr, nullptr, N, DD, 0, 1);
        // batchnorm + relu -> h; final layer emits split h for heads
        bool last = (l == 4);
        bn_apply_k<<<(unsigned)(((long)N * D4 + 255) / 256), 256>>>(
            phh, gam + l * DD, bet + l * DD, ph,
            last ? pbhi : nullptr, last ? pblo : nullptr, N);
    }

    // ---- heads: one 93-col GEMM, epilogue routes to the two output regions ----
    float* out = (float*)d_out;
    launch_mma(pbhi, pblo, pwhi + 12 * SL, pwlo + 12 * SL, phb, nullptr,
               out, out + (long)N * 87, nullptr, nullptr, N, 93, 0, 0);
}

// round 17
// speedup vs baseline: 1.2533x; 1.0483x over previous
#include <cuda_runtime.h>
#include <cuda_bf16.h>
#include <cstdint>
#include <math.h>

// Problem constants (fixed by the reference generator)
#define DD   300
#define KPAD 320          // K padded to 5 chunks of 64 bf16
#define KP8  40           // KPAD/8  (uint4 groups of 8 bf16)
#define D4   75           // DD/4    (float4 groups)
#define NMAX 100000
#define EMAX 200000
#define CAP  16           // bucket slots per node (deg ~ Poisson(2); overflow handled)
#define NW   13           // weight slots: ew2, nw2, gw1[5], gw2[5], heads
#define WSLOT (DD * KPAD) // elems per weight slot

// ---------------- scratch (device globals; no allocation allowed) ----------
__device__ float g_e   [(size_t)EMAX * DD];        // edge features  [E,D]
__device__ float g_tmp [(size_t)NMAX * DD];        // hh [N,D]
__device__ float g_h   [(size_t)NMAX * DD];        // node state h   [N,D]
__device__ float g_buf [(size_t)NMAX * DD];        // emb base for node-init addmat
__device__ float g_stats[2 * DD];                  // BN sum / sumsq
__device__ float g_hb[128];                        // concatenated head bias
__device__ __nv_bfloat16 g_ahi[(size_t)EMAX * KPAD];  // activation hi split (input A)
__device__ __nv_bfloat16 g_alo[(size_t)EMAX * KPAD];  // activation lo split
__device__ __nv_bfloat16 g_bhi[(size_t)NMAX * KPAD];  // split GEMM outputs (t1 / final h)
__device__ __nv_bfloat16 g_blo[(size_t)NMAX * KPAD];
__device__ __nv_bfloat16 g_whi[(size_t)NW * WSLOT];   // all weights^T hi split [slot][n][k]
__device__ __nv_bfloat16 g_wlo[(size_t)NW * WSLOT];   // all weights^T lo split
__device__ int g_deg[NMAX];                        // per-node incoming degree
__device__ int g_bucket[(size_t)NMAX * CAP];       // per-node edge ids
__device__ int g_ovf_cnt;                          // overflow edges (deg > CAP)
__device__ int g_ovf[4096];

// ---------------- helpers ----------------------------------------------------
__device__ __forceinline__ uint32_t smem_u32(const void* p) {
    uint32_t a;
    asm("{ .reg .u64 t; cvta.to.shared.u64 t, %1; cvt.u32.u64 %0, t; }" : "=r"(a) : "l"(p));
    return a;
}
__device__ __forceinline__ void ldsm_x4(uint32_t* r, uint32_t addr) {
    asm volatile("ldmatrix.sync.aligned.m8n8.x4.shared.b16 {%0,%1,%2,%3}, [%4];"
                 : "=r"(r[0]), "=r"(r[1]), "=r"(r[2]), "=r"(r[3]) : "r"(addr));
}
__device__ __forceinline__ void mma_bf16(float* c, const uint32_t* a, const uint32_t* b) {
    asm volatile(
        "mma.sync.aligned.m16n8k16.row.col.f32.bf16.bf16.f32 "
        "{%0,%1,%2,%3}, {%4,%5,%6,%7}, {%8,%9}, {%0,%1,%2,%3};"
        : "+f"(c[0]), "+f"(c[1]), "+f"(c[2]), "+f"(c[3])
        : "r"(a[0]), "r"(a[1]), "r"(a[2]), "r"(a[3]), "r"(b[0]), "r"(b[1]));
}
__device__ __forceinline__ void cp16(uint32_t dst, const void* src, bool valid) {
    int sz = valid ? 16 : 0;
    asm volatile("cp.async.cg.shared.global [%0], [%1], 16, %2;"
                 :: "r"(dst), "l"(src), "r"(sz) : "memory");
}
__device__ __forceinline__ void cp_commit() {
    asm volatile("cp.async.commit_group;" ::: "memory");
}
template<int NWAIT> __device__ __forceinline__ void cp_wait() {
    asm volatile("cp.async.wait_group %0;" :: "n"(NWAIT) : "memory");
}
__device__ __forceinline__ unsigned pack_bf2(float a, float b) {
    unsigned lo = __bfloat16_as_ushort(__float2bfloat16(a));
    unsigned hi = __bfloat16_as_ushort(__float2bfloat16(b));
    return (hi << 16) | lo;
}
// split 8 fp32 values into hi/lo uint4 (8 bf16 each)
__device__ __forceinline__ void split8(const float* v, uint4& uh, uint4& ul) {
    float h[8], l[8];
    #pragma unroll
    for (int j = 0; j < 8; j++) {
        __nv_bfloat16 hb = __float2bfloat16(v[j]);
        h[j] = __bfloat162float(hb);
        l[j] = v[j] - h[j];
    }
    uh = make_uint4(pack_bf2(h[0], h[1]), pack_bf2(h[2], h[3]),
                    pack_bf2(h[4], h[5]), pack_bf2(h[6], h[7]));
    ul = make_uint4(pack_bf2(l[0], l[1]), pack_bf2(l[2], l[3]),
                    pack_bf2(l[4], l[5]), pack_bf2(l[6], l[7]));
}
// split a float4 into hi/lo uint2 (4 bf16 each)
__device__ __forceinline__ void split4(float4 a, uint2& uh, uint2& ul) {
    float hx = __bfloat162float(__float2bfloat16(a.x));
    float hy = __bfloat162float(__float2bfloat16(a.y));
    float hz = __bfloat162float(__float2bfloat16(a.z));
    float hw = __bfloat162float(__float2bfloat16(a.w));
    uh = make_uint2(pack_bf2(hx, hy), pack_bf2(hz, hw));
    ul = make_uint2(pack_bf2(a.x - hx, a.y - hy), pack_bf2(a.z - hz, a.w - hw));
}

// ---------------- consolidated weight split (one launch, all 13 matrices) ----
__global__ void wsplit_all_k(const float* __restrict__ ew2, const float* __restrict__ nw2,
                             const float* __restrict__ gw1, const float* __restrict__ gw2,
                             const float* __restrict__ ahw, const float* __restrict__ chw,
                             const float* __restrict__ ahb, const float* __restrict__ chb,
                             __nv_bfloat16* __restrict__ hi, __nv_bfloat16* __restrict__ lo) {
    long idx = (long)blockIdx.x * blockDim.x + threadIdx.x;
    if (idx < 128) g_hb[idx] = (idx < 87) ? ahb[idx] : ((idx < 93) ? chb[idx - 87] : 0.f);
    if (idx >= (long)NW * WSLOT) return;
    int s = (int)(idx / WSLOT);
    int rem = (int)(idx % WSLOT);
    int n = rem / KPAD, k = rem % KPAD;
    float x = 0.f;
    if (k < DD) {
        if (s == 0)       x = ew2[(long)k * DD + n];
        else if (s == 1)  x = nw2[(long)k * DD + n];
        else if (s < 7)   x = gw1[(long)(s - 2) * DD * DD + (long)k * DD + n];
        else if (s < 12)  x = gw2[(long)(s - 7) * DD * DD + (long)k * DD + n];
        else              x = (n < 87) ? ahw[(long)k * 87 + n]
                              : ((n < 93) ? chw[(long)k * 6 + (n - 87)] : 0.f);
    }
    __nv_bfloat16 h = __float2bfloat16(x);
    hi[idx] = h;
    lo[idx] = __float2bfloat16(x - __bfloat162float(h));
}

// ---------------- pre kernels: register-resident weights, edge-group loop ----
#define PREBLK 320
#define PGRP   (PREBLK / KP8)   // 8 groups per block

// edge pre: relu(ea @ ew1 + eb1) -> split bf16 [E,KPAD]
__global__ void __launch_bounds__(PREBLK)
edge_pre_split_k(const float* __restrict__ ea, const float* __restrict__ w1,
                 const float* __restrict__ b1,
                 __nv_bfloat16* __restrict__ hi, __nv_bfloat16* __restrict__ lo, int E) {
    int u = threadIdx.x % KP8;
    long gid = (long)blockIdx.x * PGRP + threadIdx.x / KP8;
    long ngrp = (long)gridDim.x * PGRP;
    float w0[8], w1r[8], w2r[8], br[8];
    #pragma unroll
    for (int j = 0; j < 8; j++) {
        int k = u * 8 + j;
        bool ok = (k < DD);
        w0[j]  = ok ? w1[k]        : 0.f;
        w1r[j] = ok ? w1[DD + k]   : 0.f;
        w2r[j] = ok ? w1[2*DD + k] : 0.f;
        br[j]  = ok ? b1[k]        : 0.f;
    }
    for (long e = gid; e < E; e += ngrp) {
        float a0 = ea[e*3+0], a1 = ea[e*3+1], a2 = ea[e*3+2];
        float v[8];
        #pragma unroll
        for (int j = 0; j < 8; j++)
            v[j] = fmaxf(a0 * w0[j] + a1 * w1r[j] + a2 * w2r[j] + br[j], 0.f);
        uint4 uh, ul;
        split8(v, uh, ul);
        ((uint4*)hi)[e * KP8 + u] = uh;
        ((uint4*)lo)[e * KP8 + u] = ul;
    }
}

// node pre: relu(na @ nw1 + nb1) -> split; base emb[z] -> pbuf
__global__ void __launch_bounds__(PREBLK)
node_pre_split_k(const int* __restrict__ z, const float* __restrict__ ch,
                 const float* __restrict__ fc, const float* __restrict__ w1,
                 const float* __restrict__ b1, const float* __restrict__ emb,
                 __nv_bfloat16* __restrict__ hi, __nv_bfloat16* __restrict__ lo,
                 float* __restrict__ base, int N) {
    int u = threadIdx.x % KP8;
    long gid = (long)blockIdx.x * PGRP + threadIdx.x / KP8;
    long ngrp = (long)gridDim.x * PGRP;
    float w0[8], w1r[8], br[8];
    #pragma unroll
    for (int j = 0; j < 8; j++) {
        int k = u * 8 + j;
        bool ok = (k < DD);
        w0[j]  = ok ? w1[k]      : 0.f;
        w1r[j] = ok ? w1[DD + k] : 0.f;
        br[j]  = ok ? b1[k]      : 0.f;
    }
    int g0 = u * 2;
    for (long i = gid; i < N; i += ngrp) {
        float c0 = ch[i], f0 = fc[i];
        float v[8];
        #pragma unroll
        for (int j = 0; j < 8; j++)
            v[j] = fmaxf(c0 * w0[j] + f0 * w1r[j] + br[j], 0.f);
        uint4 uh, ul;
        split8(v, uh, ul);
        ((uint4*)hi)[i * KP8 + u] = uh;
        ((uint4*)lo)[i * KP8 + u] = ul;
        const float4* er = (const float4*)(emb) + (long)z[i] * D4;
        float4* brr = (float4*)(base) + i * D4;
        if (g0 < D4)     brr[g0]     = er[g0];
        if (g0 + 1 < D4) brr[g0 + 1] = er[g0 + 1];
    }
}

// ---------------- bucket build (once per launch) ------------------------------
__global__ void zero_deg_k(int N) {
    int idx = blockIdx.x * blockDim.x + threadIdx.x;
    if (idx < N) g_deg[idx] = 0;
    if (idx == 0) g_ovf_cnt = 0;
}
__global__ void fill_bucket_k(const int* __restrict__ dst, int E) {
    int e = blockIdx.x * blockDim.x + threadIdx.x;
    if (e >= E) return;
    int d = dst[e];
    int slot = atomicAdd(&g_deg[d], 1);
    if (slot < CAP) {
        g_bucket[(long)d * CAP + slot] = e;
    } else {
        int o = atomicAdd(&g_ovf_cnt, 1);
        if (o < 4096) g_ovf[o] = e;
    }
}

// ---- gather+split: A[i] = split(h[i] + sum_{e: dst=i} relu(h[src]+e)) --------
// Block 0 also zeroes ALL 2*DD g_stats entries (strided — blockDim is 256!).
__global__ void gather_split_k(const float* __restrict__ h, const float* __restrict__ e,
                               const int* __restrict__ src,
                               __nv_bfloat16* __restrict__ ahi, __nv_bfloat16* __restrict__ alo,
                               int N) {
    if (blockIdx.x == 0) {
        for (int t = threadIdx.x; t < 2 * DD; t += blockDim.x) g_stats[t] = 0.f;
    }
    int warp = (int)(((long)blockIdx.x * blockDim.x + threadIdx.x) >> 5);
    int lane = threadIdx.x & 31;
    if (warp >= N) return;
    int d = g_deg[warp];
    if (d > CAP) d = CAP;
    const float4* hr = (const float4*)(h) + (long)warp * D4;
    float4 acc[3];
    #pragma unroll
    for (int j = 0; j < 3; j++) {
        int i4 = lane + j * 32;
        acc[j] = (i4 < D4) ? hr[i4] : make_float4(0.f, 0.f, 0.f, 0.f);
    }
    for (int t = 0; t < d; t++) {
        int eid = g_bucket[(long)warp * CAP + t];
        int s = src[eid];
        const float4* hs = (const float4*)(h) + (long)s * D4;
        const float4* er = (const float4*)(e) + (long)eid * D4;
        #pragma unroll
        for (int j = 0; j < 3; j++) {
            int i4 = lane + j * 32;
            if (i4 < D4) {
                float4 a = hs[i4], b = er[i4];
                acc[j].x += fmaxf(a.x + b.x, 0.f);
                acc[j].y += fmaxf(a.y + b.y, 0.f);
                acc[j].z += fmaxf(a.z + b.z, 0.f);
                acc[j].w += fmaxf(a.w + b.w, 0.f);
            }
        }
    }
    uint2* hrow = (uint2*)(ahi + (long)warp * KPAD);
    uint2* lrow = (uint2*)(alo + (long)warp * KPAD);
    #pragma unroll
    for (int j = 0; j < 3; j++) {
        int i4 = lane + j * 32;
        if (i4 < D4) {
            uint2 uh, ul;
            split4(acc[j], uh, ul);
            hrow[i4] = uh;
            lrow[i4] = ul;
        } else if (i4 < KPAD / 4) {
            uint2 zz = make_uint2(0u, 0u);
            hrow[i4] = zz;
            lrow[i4] = zz;
        }
    }
}

// overflow fallback for nodes with deg > CAP (normally empty)
__global__ void ovf_fix_k(const float* __restrict__ h, const float* __restrict__ e,
                          const int* __restrict__ src, const int* __restrict__ dst,
                          __nv_bfloat16* __restrict__ ahi, __nv_bfloat16* __restrict__ alo) {
    int cnt = g_ovf_cnt;
    if (cnt > 4096) cnt = 4096;
    if (cnt == 0) return;
    int warp = (int)((blockIdx.x * blockDim.x + threadIdx.x) >> 5);
    int lane = threadIdx.x & 31;
    int nwarp = (gridDim.x * blockDim.x) >> 5;
    for (int t = warp; t < cnt; t += nwarp) {
        int eid = g_ovf[t];
        int s = src[eid], dd = dst[eid];
        const float* hs = h + (long)s * DD;
        const float* er = e + (long)eid * DD;
        __nv_bfloat16* hrow = ahi + (long)dd * KPAD;
        __nv_bfloat16* lrow = alo + (long)dd * KPAD;
        for (int k = lane; k < DD; k += 32) {
            float add = fmaxf(hs[k] + er[k], 0.f);
            if (add > 0.f) {
                float cur = __bfloat162float(hrow[k]) + __bfloat162float(lrow[k]);
                float nv = cur + add;
                __nv_bfloat16 hb = __float2bfloat16(nv);
                hrow[k] = hb;
                lrow[k] = __float2bfloat16(nv - __bfloat162float(hb));
            }
        }
    }
}

// ---------------- mma.sync bf16x3 GEMM, cp.async double-buffered -------------
#define BM 128
#define BN 64
#define TSTRIDE 144
#define ABYTES (BM * TSTRIDE)
#define BBYTES (BN * TSTRIDE)
#define OFF_AH 0
#define OFF_AL ABYTES
#define OFF_BH (2 * ABYTES)
#define OFF_BL (2 * ABYTES + BBYTES)
#define BUFSZ  (2 * ABYTES + 2 * BBYTES)
#define SM_DBL (2 * BUFSZ)

__device__ __forceinline__ void stage_pair(const __nv_bfloat16* __restrict__ hiP,
                                           const __nv_bfloat16* __restrict__ loP,
                                           int row0, int rowMax, int kc,
                                           uint32_t sH, uint32_t sL, int rows, int tid) {
    int total = rows * 8;
    for (int i = tid; i < total; i += 256) {
        int row = i >> 3, u = i & 7;
        int gr = row0 + row;
        bool valid = (gr < rowMax);
        long goff = (long)(valid ? gr : 0) * KPAD + kc + u * 8;
        uint32_t soff = (uint32_t)(row * TSTRIDE + u * 16);
        cp16(sH + soff, hiP + goff, valid);
        cp16(sL + soff, loP + goff, valid);
    }
}

__global__ void __launch_bounds__(256, 2)
mmagemm_k(const __nv_bfloat16* __restrict__ Ahi, const __nv_bfloat16* __restrict__ Alo,
          const __nv_bfloat16* __restrict__ Whi, const __nv_bfloat16* __restrict__ Wlo,
          const float* __restrict__ bias, const float* __restrict__ addmat,
          float* __restrict__ C, float* __restrict__ C2,
          __nv_bfloat16* __restrict__ Ohi, __nv_bfloat16* __restrict__ Olo,
          int M, int Nout, int doRelu, int doStats) {
    extern __shared__ char sm[];
    const uint32_t sbase = smem_u32(sm);
    const int tid = threadIdx.x, wid = tid >> 5, lane = tid & 31;
    const int wm = wid & 3, wn = wid >> 2;
    const int m0 = blockIdx.y * BM, n0 = blockIdx.x * BN;

    float acc[2][4][4];
    #pragma unroll
    for (int i = 0; i < 2; i++)
        #pragma unroll
        for (int j = 0; j < 4; j++)
            #pragma unroll
            for (int q = 0; q < 4; q++) acc[i][j][q] = 0.f;

    const int a_row = lane & 15;
    const int a_kh  = lane >> 4;
    const int b_nin = (lane & 7) + ((lane >> 4) << 3);
    const int b_kh  = (lane >> 3) & 1;
    const uint32_t aLane = (uint32_t)((wm * 32 + a_row) * TSTRIDE + a_kh * 16);
    const uint32_t bLane = (uint32_t)((wn * 32 + b_nin) * TSTRIDE + b_kh * 16);

    stage_pair(Ahi, Alo, m0, M,    0, sbase + OFF_AH, sbase + OFF_AL, BM, tid);
    stage_pair(Whi, Wlo, n0, Nout, 0, sbase + OFF_BH, sbase + OFF_BL, BN, tid);
    cp_commit();

    #pragma unroll
    for (int c = 0; c < 5; c++) {
        if (c < 4) {
            uint32_t nb = sbase + (uint32_t)(((c + 1) & 1) * BUFSZ);
            int kc = (c + 1) * 64;
            stage_pair(Ahi, Alo, m0, M,    kc, nb + OFF_AH, nb + OFF_AL, BM, tid);
            stage_pair(Whi, Wlo, n0, Nout, kc, nb + OFF_BH, nb + OFF_BL, BN, tid);
            cp_commit();
            cp_wait<1>();
        } else {
            cp_wait<0>();
        }
        __syncthreads();

        const uint32_t base = sbase + (uint32_t)((c & 1) * BUFSZ);
        const uint32_t aB = base + aLane, bB = base + bLane;
        #pragma unroll
        for (int ks = 0; ks < 4; ks++) {
            uint32_t ah[2][4], al[2][4];
            #pragma unroll
            for (int i = 0; i < 2; i++) {
                ldsm_x4(ah[i], aB + OFF_AH + i * (16 * TSTRIDE) + ks * 32);
                ldsm_x4(al[i], aB + OFF_AL + i * (16 * TSTRIDE) + ks * 32);
            }
            uint32_t bh[4][2], bl[4][2];
            #pragma unroll
            for (int jj = 0; jj < 2; jj++) {
                uint32_t t[4];
                ldsm_x4(t, bB + OFF_BH + jj * (16 * TSTRIDE) + ks * 32);
                bh[2*jj][0] = t[0]; bh[2*jj][1] = t[1];
                bh[2*jj+1][0] = t[2]; bh[2*jj+1][1] = t[3];
                ldsm_x4(t, bB + OFF_BL + jj * (16 * TSTRIDE) + ks * 32);
                bl[2*jj][0] = t[0]; bl[2*jj][1] = t[1];
                bl[2*jj+1][0] = t[2]; bl[2*jj+1][1] = t[3];
            }
            #pragma unroll
            for (int i = 0; i < 2; i++)
                #pragma unroll
                for (int j = 0; j < 4; j++) {
                    mma_bf16(acc[i][j], ah[i], bh[j]);
                    mma_bf16(acc[i][j], ah[i], bl[j]);
                    mma_bf16(acc[i][j], al[i], bh[j]);
                }
        }
        __syncthreads();
    }

    // epilogue (+ optional per-column BN statistics)
    const int g  = lane >> 2, tig = lane & 3;
    float cs[8], cq[8];
    #pragma unroll
    for (int t = 0; t < 8; t++) { cs[t] = 0.f; cq[t] = 0.f; }

    #pragma unroll
    for (int i = 0; i < 2; i++) {
        #pragma unroll
        for (int j = 0; j < 4; j++) {
            int row = m0 + wm * 32 + i * 16 + g;
            int col = n0 + wn * 32 + j * 8 + tig * 2;
            #pragma unroll
            for (int half = 0; half < 2; half++) {
                int r = row + half * 8;
                if (r >= M) continue;
                #pragma unroll
                for (int q = 0; q < 2; q++) {
                    int cc = col + q;
                    if (cc >= Nout) continue;
                    float v = acc[i][j][half * 2 + q] + bias[cc];
                    if (addmat) v += addmat[(long)r * Nout + cc];
                    if (doRelu) v = fmaxf(v, 0.f);
                    if (doStats) { cs[j*2+q] += v; cq[j*2+q] += v * v; }
                    if (Ohi) {
                        __nv_bfloat16 hv = __float2bfloat16(v);
                        Ohi[(long)r * KPAD + cc] = hv;
                        Olo[(long)r * KPAD + cc] = __float2bfloat16(v - __bfloat162float(hv));
                    } else if (C2) {
                        if (cc < 87) C[(long)r * 87 + cc] = v;
                        else         C2[(long)r * 6 + (cc - 87)] = v;
                    } else {
                        C[(long)r * Nout + cc] = v;
                    }
                }
            }
        }
    }

    if (doStats) {
        #pragma unroll
        for (int t = 0; t < 8; t++) {
            #pragma unroll
            for (int off = 16; off >= 4; off >>= 1) {
                cs[t] += __shfl_down_sync(0xFFFFFFFFu, cs[t], off);
                cq[t] += __shfl_down_sync(0xFFFFFFFFu, cq[t], off);
            }
        }
        float* ssm = (float*)sm;
        __syncthreads();
        if (tid < 128) ssm[tid] = 0.f;
        __syncthreads();
        if (g == 0) {
            #pragma unroll
            for (int j = 0; j < 4; j++)
                #pragma unroll
                for (int q = 0; q < 2; q++) {
                    int cl = wn * 32 + j * 8 + tig * 2 + q;
                    atomicAdd(&ssm[cl * 2 + 0], cs[j*2+q]);
                    atomicAdd(&ssm[cl * 2 + 1], cq[j*2+q]);
                }
        }
        __syncthreads();
        if (tid < 64) {
            int cc = n0 + tid;
            if (cc < DD) {
                atomicAdd(&g_stats[cc],      ssm[tid * 2 + 0]);
                atomicAdd(&g_stats[DD + cc], ssm[tid * 2 + 1]);
            }
        }
    }
}

// ---------------- misc elementwise kernels ----------------------------------
// h = relu(bn(hh)); optional split output (final layer -> heads)
__global__ void bn_apply_k(const float* __restrict__ hh, const float* __restrict__ gamma,
                           const float* __restrict__ beta, float* __restrict__ h,
                           __nv_bfloat16* __restrict__ ohi, __nv_bfloat16* __restrict__ olo,
                           int N) {
    long idx = (long)blockIdx.x * blockDim.x + threadIdx.x;
    if (idx >= (long)N * D4) return;
    int du = (int)(idx % D4);
    long r = idx / D4;
    float invN = 1.f / (float)N;
    float4 x = ((const float4*)hh)[idx];
    float o[4] = {x.x, x.y, x.z, x.w};
    #pragma unroll
    for (int c = 0; c < 4; c++) {
        int d = du * 4 + c;
        float mu  = g_stats[d] * invN;
        float var = g_stats[DD + d] * invN - mu * mu;
        float rstd = rsqrtf(var + 1e-5f);
        float v = (o[c] - mu) * rstd * gamma[d] + beta[d];
        o[c] = fmaxf(v, 0.f);
    }
    ((float4*)h)[idx] = make_float4(o[0], o[1], o[2], o[3]);
    if (ohi) {
        long base = r * KPAD + du * 4;
        uint2 uh, ul;
        split4(make_float4(o[0], o[1], o[2], o[3]), uh, ul);
        *(uint2*)(ohi + base) = uh;
        *(uint2*)(olo + base) = ul;
    }
}

// ---------------- driver ----------------------------------------------------
static void launch_mma(const __nv_bfloat16* ahi, const __nv_bfloat16* alo,
                       const __nv_bfloat16* whi, const __nv_bfloat16* wlo,
                       const float* bias, const float* addmat,
                       float* C, float* C2,
                       __nv_bfloat16* ohi, __nv_bfloat16* olo,
                       int M, int Nout, int relu, int stats) {
    dim3 grid((Nout + BN - 1) / BN, (M + BM - 1) / BM);
    mmagemm_k<<<grid, 256, SM_DBL>>>(ahi, alo, whi, wlo, bias, addmat,
                                     C, C2, ohi, olo, M, Nout, relu, stats);
}

extern "C" void kernel_launch(void* const* d_in, const int* in_sizes, int n_in,
                              void* d_out, int out_size) {
    const int*   z    = (const int*)  d_in[0];
    const float* chir = (const float*)d_in[1];
    const float* fchg = (const float*)d_in[2];
    const int*   ei   = (const int*)  d_in[3];
    const float* ea   = (const float*)d_in[4];
    const float* emb  = (const float*)d_in[5];
    const float* nw1  = (const float*)d_in[6];
    const float* nb1  = (const float*)d_in[7];
    const float* nw2  = (const float*)d_in[8];
    const float* nb2  = (const float*)d_in[9];
    const float* ew1  = (const float*)d_in[10];
    const float* eb1  = (const float*)d_in[11];
    const float* ew2  = (const float*)d_in[12];
    const float* eb2  = (const float*)d_in[13];
    const float* gw1  = (const float*)d_in[14];
    const float* gb1  = (const float*)d_in[15];
    const float* gw2  = (const float*)d_in[16];
    const float* gb2  = (const float*)d_in[17];
    const float* gam  = (const float*)d_in[18];
    const float* bet  = (const float*)d_in[19];
    const float* ahw  = (const float*)d_in[20];
    const float* ahb  = (const float*)d_in[21];
    const float* chw  = (const float*)d_in[22];
    const float* chb  = (const float*)d_in[23];

    const int N = in_sizes[0];
    const int E = in_sizes[3] / 2;
    const int* src = ei;
    const int* dst = ei + E;

    static int smem_set = 0;
    if (!smem_set) {
        cudaFuncSetAttribute(mmagemm_k, cudaFuncAttributeMaxDynamicSharedMemorySize, SM_DBL);
        smem_set = 1;
    }

    float *pe, *phh, *ph, *pbuf, *phb;
    __nv_bfloat16 *pahi, *palo, *pbhi, *pblo, *pwhi, *pwlo;
    cudaGetSymbolAddress((void**)&pe,   g_e);
    cudaGetSymbolAddress((void**)&phh,  g_tmp);
    cudaGetSymbolAddress((void**)&ph,   g_h);
    cudaGetSymbolAddress((void**)&pbuf, g_buf);
    cudaGetSymbolAddress((void**)&phb,  g_hb);
    cudaGetSymbolAddress((void**)&pahi, g_ahi);
    cudaGetSymbolAddress((void**)&palo, g_alo);
    cudaGetSymbolAddress((void**)&pbhi, g_bhi);
    cudaGetSymbolAddress((void**)&pblo, g_blo);
    cudaGetSymbolAddress((void**)&pwhi, g_whi);
    cudaGetSymbolAddress((void**)&pwlo, g_wlo);

    // ---- one-shot: bucket build + all weight splits ----
    zero_deg_k<<<(N + 255) / 256, 256>>>(N);
    fill_bucket_k<<<(E + 255) / 256, 256>>>(dst, E);
    wsplit_all_k<<<(unsigned)(((long)NW * WSLOT + 255) / 256), 256>>>(
        ew2, nw2, gw1, gw2, ahw, chw, ahb, chb, pwhi, pwlo);

    const long SL = WSLOT;

    // ---- edge encoder: e = relu(ea @ ew1 + eb1) @ ew2 + eb2 ----
    edge_pre_split_k<<<1024, PREBLK>>>(ea, ew1, eb1, pahi, palo, E);
    launch_mma(pahi, palo, pwhi, pwlo, eb2, nullptr,
               pe, nullptr, nullptr, nullptr, E, DD, 0, 0);

    // ---- node init: h = emb[z] + relu(na @ nw1 + nb1) @ nw2 + nb2 ----
    node_pre_split_k<<<1024, PREBLK>>>(z, chir, fchg, nw1, nb1, emb, pahi, palo, pbuf, N);
    launch_mma(pahi, palo, pwhi + SL, pwlo + SL, nb2, pbuf,
               ph, nullptr, nullptr, nullptr, N, DD, 0, 0);

    // ---- 5 GINE layers ----
    const unsigned GATHER_BLK = (unsigned)(((long)N * 32 + 255) / 256);
    for (int l = 0; l < 5; l++) {
        // A = split(h + sum relu(h[src]+e)); also zeroes BN stats
        gather_split_k<<<GATHER_BLK, 256>>>(ph, pe, src, pahi, palo, N);
        ovf_fix_k<<<16, 256>>>(ph, pe, src, dst, pahi, palo);
        // GEMM1: t1 = relu(A @ W1 + b1) -> split bhi/blo
        launch_mma(pahi, palo, pwhi + (2 + l) * SL, pwlo + (2 + l) * SL,
                   gb1 + l * DD, nullptr,
                   nullptr, nullptr, pbhi, pblo, N, DD, 1, 0);
        // GEMM2: hh = t1 @ W2 + b2 (fp32 out, fused BN stats)
        launch_mma(pbhi, pblo, pwhi + (7 + l) * SL, pwlo + (7 + l) * SL,
                   gb2 + l * DD, nullptr,
                   phh, nullptr, nullptr, nullptr, N, DD, 0, 1);
        // batchnorm + relu -> h; final layer emits split h for heads
        bool last = (l == 4);
        bn_apply_k<<<(unsigned)(((long)N * D4 + 255) / 256), 256>>>(
            phh, gam + l * DD, bet + l * DD, ph,
            last ? pbhi : nullptr, last ? pblo : nullptr, N);
    }

    // ---- heads: one 93-col GEMM, epilogue routes to the two output regions ----
    float* out = (float*)d_out;
    launch_mma(pbhi, pblo, pwhi + 12 * SL, pwlo + 12 * SL, phb, nullptr,
               out, out + (long)N * 87, nullptr, nullptr, N, 93, 0, 0);
}